// round 8
// baseline (speedup 1.0000x reference)
#include <cuda_runtime.h>
#include <cuda_fp16.h>
#include <cstdint>
#include <math.h>

#define BB 2
#define S_IMG 1024
#define S_TXT 512
#define SEQ 1536
#define DIM 3072
#define HEADS 24
#define HD 128
#define EPSF 1e-6f
#define SCALEF 0.08838834764831845f

// Scratch (device globals -- no allocation allowed)
__device__ float g_QJ[BB * SEQ * DIM];
__device__ float g_KJ[BB * SEQ * DIM];
__device__ float g_VJ[BB * SEQ * DIM];
__device__ __half g_Whi[8 * DIM * DIM];
__device__ __half g_Wlo[8 * DIM * DIM];
__device__ __half g_Xhi[BB * SEQ * DIM];
__device__ __half g_Qhi[BB * SEQ * DIM];
__device__ __half g_Qlo[BB * SEQ * DIM];
__device__ __half g_Khi[BB * SEQ * DIM];
__device__ __half g_Klo[BB * SEQ * DIM];
__device__ __half g_Vhi[BB * SEQ * DIM];
__device__ __half g_Vlo[BB * SEQ * DIM];

// ===========================================================================
// helpers
// ===========================================================================
__device__ __forceinline__ uint32_t smem_u32(const void* p) {
    uint32_t a;
    asm("{ .reg .u64 t; cvta.to.shared.u64 t, %1; cvt.u32.u64 %0, t; }"
        : "=r"(a) : "l"(p));
    return a;
}
#define LDM4(r, a) \
    asm volatile("ldmatrix.sync.aligned.m8n8.x4.shared.b16 {%0,%1,%2,%3}, [%4];" \
        : "=r"((r)[0]), "=r"((r)[1]), "=r"((r)[2]), "=r"((r)[3]) : "r"(a))
#define LDM4T(r, a) \
    asm volatile("ldmatrix.sync.aligned.m8n8.x4.trans.shared.b16 {%0,%1,%2,%3}, [%4];" \
        : "=r"((r)[0]), "=r"((r)[1]), "=r"((r)[2]), "=r"((r)[3]) : "r"(a))
#define MMA_F16(d, a, b0, b1) \
    asm volatile("mma.sync.aligned.m16n8k16.row.col.f32.f16.f16.f32 " \
        "{%0,%1,%2,%3}, {%4,%5,%6,%7}, {%8,%9}, {%0,%1,%2,%3};" \
        : "+f"((d)[0]), "+f"((d)[1]), "+f"((d)[2]), "+f"((d)[3]) \
        : "r"((a)[0]), "r"((a)[1]), "r"((a)[2]), "r"((a)[3]), "r"(b0), "r"(b1))
#define CPA16(dst, src) \
    asm volatile("cp.async.cg.shared.global [%0], [%1], 16;" :: "r"(dst), "l"(src))
#define CP_COMMIT() asm volatile("cp.async.commit_group;" ::: "memory")
#define CP_WAIT(n)  asm volatile("cp.async.wait_group %0;" :: "n"(n) : "memory")

__device__ __forceinline__ uint32_t pack_h2(float a, float b) {
    __half2 h = __floats2half2_rn(a, b);
    return *(uint32_t*)&h;
}
__device__ __forceinline__ void split2(float a, float b, uint32_t& hi, uint32_t& lo) {
    __half ha = __float2half_rn(a), hb = __float2half_rn(b);
    __half la = __float2half_rn(a - __half2float(ha));
    __half lb = __float2half_rn(b - __half2float(hb));
    hi = ((uint32_t)__half_as_ushort(hb) << 16) | __half_as_ushort(ha);
    lo = ((uint32_t)__half_as_ushort(lb) << 16) | __half_as_ushort(la);
}
__device__ __forceinline__ void split_f16x4(float4 v, uint2& ph, uint2& pl) {
    split2(v.x, v.y, ph.x, pl.x);
    split2(v.z, v.w, ph.y, pl.y);
}

// ---------------------------------------------------------------------------
// conversion kernels
// ---------------------------------------------------------------------------
// merged weight split: grid.y selects the weight matrix
__global__ void __launch_bounds__(256) split_w8_kernel(
    const float4* __restrict__ w0, const float4* __restrict__ w1,
    const float4* __restrict__ w2, const float4* __restrict__ w3,
    const float4* __restrict__ w4, const float4* __restrict__ w5,
    const float4* __restrict__ w6, const float4* __restrict__ w7,
    uint2* __restrict__ hi, uint2* __restrict__ lo, int n4)
{
    int i = blockIdx.x * 256 + threadIdx.x;
    int z = blockIdx.y;
    if (i < n4) {
        const float4* src = (z == 0) ? w0 : (z == 1) ? w1 : (z == 2) ? w2 : (z == 3) ? w3
                          : (z == 4) ? w4 : (z == 5) ? w5 : (z == 6) ? w6 : w7;
        uint2 ph, pl;
        split_f16x4(src[i], ph, pl);
        hi[(size_t)z * n4 + i] = ph;
        lo[(size_t)z * n4 + i] = pl;
    }
}

// fp32 [BB][rpb][DIM] -> fp16 hi only, joint rows (b*SEQ + dst_off + s)
__global__ void __launch_bounds__(256) conv_hi_kernel(
    const float4* __restrict__ src, uint2* __restrict__ hi, int rpb, int dst_off)
{
    int i = blockIdx.x * 256 + threadIdx.x;
    int n4 = BB * rpb * (DIM / 4);
    if (i < n4) {
        int q = i % (DIM / 4);
        int row = i / (DIM / 4);
        int b = row / rpb, s = row % rpb;
        float4 v = src[i];
        uint2 ph;
        ph.x = pack_h2(v.x, v.y);
        ph.y = pack_h2(v.z, v.w);
        hi[(b * SEQ + dst_off + s) * (DIM / 4) + q] = ph;
    }
}

// ===========================================================================
// fp16 2-pass GEMM, tile 128x256: C = A @ W + bias; A hi fp16, W hi/lo fp16.
// Warps 2M x 4N (64 rows x 64 cols each). KC=32, 4-stage cp.async.
// z==2 with vhi != null: write fp16 hi/lo split instead of fp32 (V path).
// ===========================================================================
#define KC 32
#define CHUNKS (DIM / KC)                  // 96
#define A_ST2 80
#define B_ST2 528                           // 512B data + 16 pad
#define A_TILE_B (128 * A_ST2)              // 10240
#define B_TILE_B (32 * B_ST2)               // 16896
#define OFF_BHI A_TILE_B
#define OFF_BLO (A_TILE_B + B_TILE_B)
#define STAGE_B (A_TILE_B + 2 * B_TILE_B)   // 44032
#define NSTAGE 4
#define GEMM_SMEM_BYTES (NSTAGE * STAGE_B)  // 176128

__global__ void __launch_bounds__(256) mma_gemm_kernel(
    const __half* __restrict__ Ahi_g, int a_off, int rpb,
    const __half* __restrict__ Whi_base, const __half* __restrict__ Wlo_base,
    int w0, int w1, int w2,
    const float* bias0, const float* bias1, const float* bias2,
    float* C0, float* C1, float* C2,
    __half* __restrict__ vhi, __half* __restrict__ vlo,
    int c_seq, int c_off)
{
    extern __shared__ __align__(128) char smem[];
    const uint32_t sbase = smem_u32(smem);
    const int tid = threadIdx.x;
    const int wid = tid >> 5, lane = tid & 31;
    const int warp_m = wid >> 2;           // 2 groups of 64 rows
    const int warp_n = wid & 3;            // 4 groups of 64 cols
    const int z = blockIdx.z;

    const int widx = (z == 0) ? w0 : ((z == 1) ? w1 : w2);
    const float* bias = (z == 0) ? bias0 : ((z == 1) ? bias1 : bias2);
    float* C_base = (z == 0) ? C0 : ((z == 1) ? C1 : C2);
    const __half* Whi = Whi_base + (size_t)widx * DIM * DIM;
    const __half* Wlo = Wlo_base + (size_t)widx * DIM * DIM;

    const int row0 = blockIdx.y * 128;
    const int col0 = blockIdx.x * 256;
    const int b  = row0 / rpb;
    const int s0 = row0 % rpb;
    const __half* Ahi = Ahi_g + (size_t)(b * SEQ + a_off + s0) * DIM;
    const size_t crow0 = (size_t)(b * c_seq + c_off + s0);
    float* C = C_base + crow0 * DIM;

#define ISSUE(c) do { \
    const int k0 = (c) * KC; \
    const uint32_t stb = sbase + ((c) % NSTAGE) * STAGE_B; \
    _Pragma("unroll") \
    for (int i = 0; i < 2; i++) { \
        int f = tid + i * 256; \
        uint32_t d = stb + (uint32_t)(f >> 2) * A_ST2 + (f & 3) * 16; \
        size_t so = (size_t)(f >> 2) * DIM + k0 + ((f & 3) << 3); \
        CPA16(d, (const void*)(Ahi + so)); \
    } \
    _Pragma("unroll") \
    for (int i = 0; i < 4; i++) { \
        int f = tid + i * 256; \
        uint32_t db = stb + OFF_BHI + (uint32_t)(f >> 5) * B_ST2 + (f & 31) * 16; \
        size_t sb2 = (size_t)(k0 + (f >> 5)) * DIM + col0 + ((f & 31) << 3); \
        CPA16(db, (const void*)(Whi + sb2)); \
        CPA16(db + B_TILE_B, (const void*)(Wlo + sb2)); \
    } \
    CP_COMMIT(); \
} while (0)

    float acc[4][8][4];
#pragma unroll
    for (int i = 0; i < 4; i++)
#pragma unroll
        for (int j = 0; j < 8; j++)
#pragma unroll
            for (int k = 0; k < 4; k++) acc[i][j][k] = 0.f;

    const uint32_t a_row = (uint32_t)(warp_m * 64 + (lane & 15));
    const uint32_t a_sel = (uint32_t)((lane >> 4) * 16);
    const uint32_t b_row = (uint32_t)(lane & 15);
    const uint32_t b_sel = (uint32_t)(warp_n * 128 + ((lane >> 4) * 16));

#define COMPUTE(sidx) do { \
    const uint32_t sb = sbase + (sidx) * STAGE_B; \
    _Pragma("unroll") \
    for (int ks = 0; ks < 2; ks++) { \
        uint32_t ah[4][4]; \
        _Pragma("unroll") \
        for (int mt = 0; mt < 4; mt++) { \
            uint32_t ad = sb + (a_row + mt * 16) * A_ST2 + ks * 32 + a_sel; \
            LDM4(ah[mt], ad); \
        } \
        _Pragma("unroll") \
        for (int ng = 0; ng < 4; ng++) { \
            uint32_t bh[4], bl[4]; \
            uint32_t bd = sb + OFF_BHI + (ks * 16 + b_row) * B_ST2 + b_sel + ng * 32; \
            LDM4T(bh, bd); \
            LDM4T(bl, bd + B_TILE_B); \
            _Pragma("unroll") \
            for (int mt = 0; mt < 4; mt++) { \
                MMA_F16(acc[mt][ng * 2 + 0], ah[mt], bh[0], bh[1]); \
                MMA_F16(acc[mt][ng * 2 + 0], ah[mt], bl[0], bl[1]); \
                MMA_F16(acc[mt][ng * 2 + 1], ah[mt], bh[2], bh[3]); \
                MMA_F16(acc[mt][ng * 2 + 1], ah[mt], bl[2], bl[3]); \
            } \
        } \
    } \
} while (0)

    ISSUE(0); ISSUE(1); ISSUE(2);
    for (int c = 0; c < CHUNKS; c++) {
        if (c < CHUNKS - 2) { CP_WAIT(2); }
        else if (c == CHUNKS - 2) { CP_WAIT(1); }
        else { CP_WAIT(0); }
        __syncthreads();
        if (c + 3 < CHUNKS) ISSUE(c + 3);
        COMPUTE(c % NSTAGE);
    }

    const int m_base = warp_m * 64;
    const int n_base = col0 + warp_n * 64;
    const bool v_out = (z == 2) && (vhi != nullptr);
#pragma unroll
    for (int mt = 0; mt < 4; mt++) {
#pragma unroll
        for (int nt = 0; nt < 8; nt++) {
            int r  = m_base + mt * 16 + (lane >> 2);
            int cc = n_base + nt * 8 + ((lane & 3) << 1);
            float b0 = bias[cc], b1 = bias[cc + 1];
            float v00 = acc[mt][nt][0] + b0, v01 = acc[mt][nt][1] + b1;
            float v10 = acc[mt][nt][2] + b0, v11 = acc[mt][nt][3] + b1;
            if (v_out) {
                uint32_t h0, l0, h1, l1;
                split2(v00, v01, h0, l0);
                split2(v10, v11, h1, l1);
                *(uint32_t*)(vhi + (crow0 + r) * DIM + cc) = h0;
                *(uint32_t*)(vlo + (crow0 + r) * DIM + cc) = l0;
                *(uint32_t*)(vhi + (crow0 + r + 8) * DIM + cc) = h1;
                *(uint32_t*)(vlo + (crow0 + r + 8) * DIM + cc) = l1;
            } else {
                *(float2*)(C + (size_t)r * DIM + cc) = make_float2(v00, v01);
                *(float2*)(C + (size_t)(r + 8) * DIM + cc) = make_float2(v10, v11);
            }
        }
    }
#undef ISSUE
#undef COMPUTE
}

// ---------------------------------------------------------------------------
// Fused RMS-norm + RoPE; reads fp32 Q/K, writes fp16 hi/lo splits.
// ---------------------------------------------------------------------------
__global__ void __launch_bounds__(128) rmsrope_kernel(
    const float* __restrict__ Q, const float* __restrict__ K,
    __half* __restrict__ Qhi, __half* __restrict__ Qlo,
    __half* __restrict__ Khi, __half* __restrict__ Klo,
    const float* __restrict__ cosb, const float* __restrict__ sinb,
    const float* __restrict__ gq, const float* __restrict__ gk,
    const float* __restrict__ gqc, const float* __restrict__ gkc)
{
    const int idx = blockIdx.x;
    const int h = idx % HEADS;
    const int s = (idx / HEADS) % SEQ;
    const int b = idx / (HEADS * SEQ);
    const int d = threadIdx.x;
    const size_t off = ((size_t)(b * SEQ + s)) * DIM + h * HD + d;
    __shared__ float sh[HD];
    __shared__ float red[4];
    const float c  = cosb[s * (HD / 2) + (d >> 1)];
    const float sn = sinb[s * (HD / 2) + (d >> 1)];
    const bool txt = (s < S_TXT);

    {
        float v = Q[off];
        float sq = v * v;
#pragma unroll
        for (int o = 16; o > 0; o >>= 1) sq += __shfl_xor_sync(0xffffffffu, sq, o);
        if ((d & 31) == 0) red[d >> 5] = sq;
        __syncthreads();
        float mean = (red[0] + red[1] + red[2] + red[3]) * (1.0f / HD);
        float scl = rsqrtf(mean + EPSF) * (txt ? gqc[d] : gq[d]);
        sh[d] = v * scl;
        __syncthreads();
        float out = ((d & 1) == 0) ? (sh[d] * c - sh[d + 1] * sn)
                                   : (sh[d - 1] * sn + sh[d] * c);
        __half hh = __float2half_rn(out);
        Qhi[off] = hh;
        Qlo[off] = __float2half_rn(out - __half2float(hh));
    }
    __syncthreads();
    {
        float v = K[off];
        float sq = v * v;
#pragma unroll
        for (int o = 16; o > 0; o >>= 1) sq += __shfl_xor_sync(0xffffffffu, sq, o);
        if ((d & 31) == 0) red[d >> 5] = sq;
        __syncthreads();
        float mean = (red[0] + red[1] + red[2] + red[3]) * (1.0f / HD);
        float scl = rsqrtf(mean + EPSF) * (txt ? gkc[d] : gk[d]);
        sh[d] = v * scl;
        __syncthreads();
        float out = ((d & 1) == 0) ? (sh[d] * c - sh[d + 1] * sn)
                                   : (sh[d - 1] * sn + sh[d] * c);
        __half hh = __float2half_rn(out);
        Khi[off] = hh;
        Klo[off] = __float2half_rn(out - __half2float(hh));
    }
}

// ===========================================================================
// Flash attention via mma.sync fp16 (unchanged from R7 pass).
// QK^T 3-pass (hi/lo), PV 2-pass (P hi). Output hi-only to Xhi.
// ===========================================================================
#define FROW_B 272
#define FK_HI 0
#define FK_LO (32 * FROW_B)
#define FV_HI (2 * 32 * FROW_B)
#define FV_LO (3 * 32 * FROW_B)
#define FSTAGE_B (4 * 32 * FROW_B)
#define FNSTAGE 3
#define FLASH_SMEM_BYTES (FNSTAGE * FSTAGE_B)
#define FITERS (SEQ / 32)

__global__ void __launch_bounds__(256) flash_mma_kernel(
    const __half* __restrict__ Qhi_g, const __half* __restrict__ Qlo_g,
    const __half* __restrict__ Khi_g, const __half* __restrict__ Klo_g,
    const __half* __restrict__ Vhi_g, const __half* __restrict__ Vlo_g,
    __half* __restrict__ Ohi)
{
    extern __shared__ __align__(128) char smem[];
    const uint32_t sbase = smem_u32(smem);
    const int tid = threadIdx.x;
    const int wq = tid >> 5, lane = tid & 31;
    const int q0 = blockIdx.x * 128;
    const int bh = blockIdx.y;
    const int b = bh / HEADS, h = bh % HEADS;
    const size_t hoff = (size_t)h * HD;

    {
#pragma unroll
        for (int i = 0; i < 8; i++) {
            int f = tid + i * 256;
            int r = f >> 4, c = f & 15;
            uint32_t d = sbase + (uint32_t)r * FROW_B + c * 16;
            size_t so = (size_t)(b * SEQ + q0 + r) * DIM + hoff + c * 8;
            CPA16(d, (const void*)(Qhi_g + so));
            CPA16(d + 34816, (const void*)(Qlo_g + so));
        }
        CP_COMMIT();
        CP_WAIT(0);
        __syncthreads();
    }
    uint32_t qh[8][4], ql[8][4];
    {
        const uint32_t qrow = (uint32_t)(wq * 16 + (lane & 15));
        const uint32_t qc8  = (uint32_t)((lane >> 4) * 16);
#pragma unroll
        for (int ks = 0; ks < 8; ks++) {
            uint32_t ad = sbase + qrow * FROW_B + ks * 32 + qc8;
            LDM4(qh[ks], ad);
            LDM4(ql[ks], ad + 34816);
        }
    }
    __syncthreads();

#define FISSUE(kt) do { \
    const int k0 = (kt) * 32; \
    const uint32_t stb = sbase + ((kt) % FNSTAGE) * FSTAGE_B; \
    _Pragma("unroll") \
    for (int i = 0; i < 2; i++) { \
        int f = tid + i * 256; \
        int r = f >> 4, c = f & 15; \
        uint32_t d = stb + (uint32_t)r * FROW_B + c * 16; \
        size_t so = (size_t)(b * SEQ + k0 + r) * DIM + hoff + c * 8; \
        CPA16(d + FK_HI, (const void*)(Khi_g + so)); \
        CPA16(d + FK_LO, (const void*)(Klo_g + so)); \
        CPA16(d + FV_HI, (const void*)(Vhi_g + so)); \
        CPA16(d + FV_LO, (const void*)(Vlo_g + so)); \
    } \
    CP_COMMIT(); \
} while (0)

    float acc[16][4];
#pragma unroll
    for (int i = 0; i < 16; i++)
#pragma unroll
        for (int j = 0; j < 4; j++) acc[i][j] = 0.f;
    float m0 = -1e30f, m1 = -1e30f, l0 = 0.f, l1 = 0.f;

    const uint32_t krow = (uint32_t)(lane & 15);
    const uint32_t kc8  = (uint32_t)((lane >> 4) * 16);

    FISSUE(0); FISSUE(1);
    for (int kt = 0; kt < FITERS; kt++) {
        if (kt == FITERS - 1) { CP_WAIT(0); } else { CP_WAIT(1); }
        __syncthreads();
        if (kt + 2 < FITERS) FISSUE(kt + 2);
        const uint32_t stb = sbase + (kt % FNSTAGE) * FSTAGE_B;

        float s[4][4];
#pragma unroll
        for (int i = 0; i < 4; i++)
#pragma unroll
            for (int j = 0; j < 4; j++) s[i][j] = 0.f;
#pragma unroll
        for (int ks = 0; ks < 8; ks++) {
#pragma unroll
            for (int half = 0; half < 2; half++) {
                uint32_t kbh[4], kbl[4];
                uint32_t kd = stb + FK_HI + (half * 16 + krow) * FROW_B + ks * 32 + kc8;
                LDM4(kbh, kd);
                LDM4(kbl, kd + FK_LO);
                MMA_F16(s[2 * half + 0], qh[ks], kbh[0], kbh[2]);
                MMA_F16(s[2 * half + 0], qh[ks], kbl[0], kbl[2]);
                MMA_F16(s[2 * half + 0], ql[ks], kbh[0], kbh[2]);
                MMA_F16(s[2 * half + 1], qh[ks], kbh[1], kbh[3]);
                MMA_F16(s[2 * half + 1], qh[ks], kbl[1], kbl[3]);
                MMA_F16(s[2 * half + 1], ql[ks], kbh[1], kbh[3]);
            }
        }
#pragma unroll
        for (int i = 0; i < 4; i++)
#pragma unroll
            for (int j = 0; j < 4; j++) s[i][j] *= SCALEF;

        float mx0 = fmaxf(fmaxf(s[0][0], s[0][1]), fmaxf(s[1][0], s[1][1]));
        mx0 = fmaxf(mx0, fmaxf(fmaxf(s[2][0], s[2][1]), fmaxf(s[3][0], s[3][1])));
        float mx1 = fmaxf(fmaxf(s[0][2], s[0][3]), fmaxf(s[1][2], s[1][3]));
        mx1 = fmaxf(mx1, fmaxf(fmaxf(s[2][2], s[2][3]), fmaxf(s[3][2], s[3][3])));
#pragma unroll
        for (int o = 1; o <= 2; o <<= 1) {
            mx0 = fmaxf(mx0, __shfl_xor_sync(0xffffffffu, mx0, o));
            mx1 = fmaxf(mx1, __shfl_xor_sync(0xffffffffu, mx1, o));
        }
        float mn0 = fmaxf(m0, mx0), mn1 = fmaxf(m1, mx1);
        float f0 = __expf(m0 - mn0), f1 = __expf(m1 - mn1);
        m0 = mn0; m1 = mn1;
        float rs0 = 0.f, rs1 = 0.f;
#pragma unroll
        for (int nt = 0; nt < 4; nt++) {
            s[nt][0] = __expf(s[nt][0] - mn0);
            s[nt][1] = __expf(s[nt][1] - mn0);
            s[nt][2] = __expf(s[nt][2] - mn1);
            s[nt][3] = __expf(s[nt][3] - mn1);
            rs0 += s[nt][0] + s[nt][1];
            rs1 += s[nt][2] + s[nt][3];
        }
#pragma unroll
        for (int o = 1; o <= 2; o <<= 1) {
            rs0 += __shfl_xor_sync(0xffffffffu, rs0, o);
            rs1 += __shfl_xor_sync(0xffffffffu, rs1, o);
        }
        l0 = l0 * f0 + rs0;
        l1 = l1 * f1 + rs1;
#pragma unroll
        for (int i = 0; i < 16; i++) {
            acc[i][0] *= f0; acc[i][1] *= f0;
            acc[i][2] *= f1; acc[i][3] *= f1;
        }

        uint32_t ph[2][4];
#pragma unroll
        for (int k2 = 0; k2 < 2; k2++) {
            ph[k2][0] = pack_h2(s[2 * k2][0],     s[2 * k2][1]);
            ph[k2][1] = pack_h2(s[2 * k2][2],     s[2 * k2][3]);
            ph[k2][2] = pack_h2(s[2 * k2 + 1][0], s[2 * k2 + 1][1]);
            ph[k2][3] = pack_h2(s[2 * k2 + 1][2], s[2 * k2 + 1][3]);
        }
#pragma unroll
        for (int ng = 0; ng < 8; ng++) {
#pragma unroll
            for (int k2 = 0; k2 < 2; k2++) {
                uint32_t vbh[4], vbl[4];
                uint32_t vd = stb + FV_HI + (k2 * 16 + krow) * FROW_B + ng * 32 + kc8;
                LDM4T(vbh, vd);
                LDM4T(vbl, vd + (FV_LO - FV_HI));
                MMA_F16(acc[2 * ng + 0], ph[k2], vbh[0], vbh[1]);
                MMA_F16(acc[2 * ng + 0], ph[k2], vbl[0], vbl[1]);
                MMA_F16(acc[2 * ng + 1], ph[k2], vbh[2], vbh[3]);
                MMA_F16(acc[2 * ng + 1], ph[k2], vbl[2], vbl[3]);
            }
        }
    }

    float inv0 = 1.0f / l0, inv1 = 1.0f / l1;
    const int r0g = b * SEQ + q0 + wq * 16 + (lane >> 2);
#pragma unroll
    for (int nt = 0; nt < 16; nt++) {
        int cc = (int)hoff + nt * 8 + ((lane & 3) << 1);
        *(uint32_t*)(Ohi + (size_t)r0g * DIM + cc) =
            pack_h2(acc[nt][0] * inv0, acc[nt][1] * inv0);
        *(uint32_t*)(Ohi + (size_t)(r0g + 8) * DIM + cc) =
            pack_h2(acc[nt][2] * inv1, acc[nt][3] * inv1);
    }
#undef FISSUE
}

// ---------------------------------------------------------------------------
extern "C" void kernel_launch(void* const* d_in, const int* in_sizes, int n_in,
                              void* d_out, int out_size)
{
    (void)in_sizes; (void)n_in; (void)out_size;
    const float* x     = (const float*)d_in[0];
    const float* ctx   = (const float*)d_in[1];
    const float* cosb  = (const float*)d_in[2];
    const float* sinb  = (const float*)d_in[3];
    const float* bq    = (const float*)d_in[5];
    const float* bk    = (const float*)d_in[7];
    const float* bv    = (const float*)d_in[9];
    const float* bqc   = (const float*)d_in[11];
    const float* bkc   = (const float*)d_in[13];
    const float* bvc   = (const float*)d_in[15];
    const float* b_out = (const float*)d_in[17];
    const float* b_add = (const float*)d_in[19];
    const float* g_q   = (const float*)d_in[20];
    const float* g_k   = (const float*)d_in[21];
    const float* g_qc  = (const float*)d_in[22];
    const float* g_kc  = (const float*)d_in[23];
    float* out = (float*)d_out;

    float *QJ, *KJ, *VJ;
    __half *Whi, *Wlo, *Xhi, *Qhi, *Qlo, *Khi, *Klo, *Vhi, *Vlo;
    cudaGetSymbolAddress((void**)&QJ, g_QJ);
    cudaGetSymbolAddress((void**)&KJ, g_KJ);
    cudaGetSymbolAddress((void**)&VJ, g_VJ);
    cudaGetSymbolAddress((void**)&Whi, g_Whi);
    cudaGetSymbolAddress((void**)&Wlo, g_Wlo);
    cudaGetSymbolAddress((void**)&Xhi, g_Xhi);
    cudaGetSymbolAddress((void**)&Qhi, g_Qhi);
    cudaGetSymbolAddress((void**)&Qlo, g_Qlo);
    cudaGetSymbolAddress((void**)&Khi, g_Khi);
    cudaGetSymbolAddress((void**)&Klo, g_Klo);
    cudaGetSymbolAddress((void**)&Vhi, g_Vhi);
    cudaGetSymbolAddress((void**)&Vlo, g_Vlo);

    cudaFuncSetAttribute(mma_gemm_kernel,
                         cudaFuncAttributeMaxDynamicSharedMemorySize, GEMM_SMEM_BYTES);
    cudaFuncSetAttribute(flash_mma_kernel,
                         cudaFuncAttributeMaxDynamicSharedMemorySize, FLASH_SMEM_BYTES);

    const int WN4 = DIM * DIM / 4;

    // preconvert all 8 weights (fp16 hi/lo), one launch
    split_w8_kernel<<<dim3((WN4 + 255) / 256, 8), 256>>>(
        (const float4*)d_in[4],  (const float4*)d_in[6],  (const float4*)d_in[8],
        (const float4*)d_in[10], (const float4*)d_in[12], (const float4*)d_in[14],
        (const float4*)d_in[16], (const float4*)d_in[18],
        (uint2*)Whi, (uint2*)Wlo, WN4);

    // preconvert activations (fp16 hi only) into joint layout
    conv_hi_kernel<<<(BB * S_TXT * (DIM / 4) + 255) / 256, 256>>>(
        (const float4*)ctx, (uint2*)Xhi, S_TXT, 0);
    conv_hi_kernel<<<(BB * S_IMG * (DIM / 4) + 255) / 256, 256>>>(
        (const float4*)x, (uint2*)Xhi, S_IMG, S_TXT);

    // QKV projections (merged z=3; z==2 (V) writes fp16 hi/lo directly)
    dim3 gImg3(DIM / 256, (BB * S_IMG) / 128, 3);
    dim3 gTxt3(DIM / 256, (BB * S_TXT) / 128, 3);
    mma_gemm_kernel<<<gImg3, 256, GEMM_SMEM_BYTES>>>(Xhi, S_TXT, S_IMG,
        Whi, Wlo, 0, 1, 2, bq, bk, bv, QJ, KJ, VJ, Vhi, Vlo, SEQ, S_TXT);
    mma_gemm_kernel<<<gTxt3, 256, GEMM_SMEM_BYTES>>>(Xhi, 0, S_TXT,
        Whi, Wlo, 3, 4, 5, bqc, bkc, bvc, QJ, KJ, VJ, Vhi, Vlo, SEQ, 0);

    // RMS+RoPE -> Q/K fp16 splits
    rmsrope_kernel<<<BB * SEQ * HEADS, 128>>>(QJ, KJ, Qhi, Qlo, Khi, Klo,
                                              cosb, sinb, g_q, g_k, g_qc, g_kc);

    // Flash attention (writes fp16 hi output into Xhi)
    flash_mma_kernel<<<dim3(SEQ / 128, BB * HEADS), 256, FLASH_SMEM_BYTES>>>(
        Qhi, Qlo, Khi, Klo, Vhi, Vlo, Xhi);

    // output projections (fp32 out)
    dim3 gTxt(DIM / 256, (BB * S_TXT) / 128, 1);
    dim3 gImg(DIM / 256, (BB * S_IMG) / 128, 1);
    mma_gemm_kernel<<<gTxt, 256, GEMM_SMEM_BYTES>>>(Xhi, 0, S_TXT,
        Whi, Wlo, 7, 7, 7, b_add, b_add, b_add, out, out, out,
        ((__half*)nullptr), ((__half*)nullptr), S_TXT, 0);
    mma_gemm_kernel<<<gImg, 256, GEMM_SMEM_BYTES>>>(Xhi, S_TXT, S_IMG,
        Whi, Wlo, 6, 6, 6, b_out, b_out, b_out,
        out + (size_t)BB * S_TXT * DIM, out + (size_t)BB * S_TXT * DIM,
        out + (size_t)BB * S_TXT * DIM,
        ((__half*)nullptr), ((__half*)nullptr), S_IMG, 0);
}

// round 10
// speedup vs baseline: 1.1140x; 1.1140x over previous
#include <cuda_runtime.h>
#include <cuda_fp16.h>
#include <cstdint>
#include <math.h>

#define BB 2
#define S_IMG 1024
#define S_TXT 512
#define SEQ 1536
#define DIM 3072
#define HEADS 24
#define HD 128
#define EPSF 1e-6f
#define SCALEF 0.08838834764831845f

// Scratch (device globals -- no allocation allowed)
__device__ __half g_Whi[8 * DIM * DIM];
__device__ __half g_Wlo[8 * DIM * DIM];
__device__ __half g_Xhi[BB * SEQ * DIM];
__device__ __half g_Qhi[BB * SEQ * DIM];
__device__ __half g_Qlo[BB * SEQ * DIM];
__device__ __half g_Khi[BB * SEQ * DIM];
__device__ __half g_Klo[BB * SEQ * DIM];
__device__ __half g_Vhi[BB * SEQ * DIM];
__device__ __half g_Vlo[BB * SEQ * DIM];

// ===========================================================================
// helpers
// ===========================================================================
__device__ __forceinline__ uint32_t smem_u32(const void* p) {
    uint32_t a;
    asm("{ .reg .u64 t; cvta.to.shared.u64 t, %1; cvt.u32.u64 %0, t; }"
        : "=r"(a) : "l"(p));
    return a;
}
#define LDM4(r, a) \
    asm volatile("ldmatrix.sync.aligned.m8n8.x4.shared.b16 {%0,%1,%2,%3}, [%4];" \
        : "=r"((r)[0]), "=r"((r)[1]), "=r"((r)[2]), "=r"((r)[3]) : "r"(a))
#define LDM4T(r, a) \
    asm volatile("ldmatrix.sync.aligned.m8n8.x4.trans.shared.b16 {%0,%1,%2,%3}, [%4];" \
        : "=r"((r)[0]), "=r"((r)[1]), "=r"((r)[2]), "=r"((r)[3]) : "r"(a))
#define MMA_F16(d, a, b0, b1) \
    asm volatile("mma.sync.aligned.m16n8k16.row.col.f32.f16.f16.f32 " \
        "{%0,%1,%2,%3}, {%4,%5,%6,%7}, {%8,%9}, {%0,%1,%2,%3};" \
        : "+f"((d)[0]), "+f"((d)[1]), "+f"((d)[2]), "+f"((d)[3]) \
        : "r"((a)[0]), "r"((a)[1]), "r"((a)[2]), "r"((a)[3]), "r"(b0), "r"(b1))
#define CPA16(dst, src) \
    asm volatile("cp.async.cg.shared.global [%0], [%1], 16;" :: "r"(dst), "l"(src))
#define CP_COMMIT() asm volatile("cp.async.commit_group;" ::: "memory")
#define CP_WAIT(n)  asm volatile("cp.async.wait_group %0;" :: "n"(n) : "memory")

__device__ __forceinline__ uint32_t pack_h2(float a, float b) {
    __half2 h = __floats2half2_rn(a, b);
    return *(uint32_t*)&h;
}
__device__ __forceinline__ void split2(float a, float b, uint32_t& hi, uint32_t& lo) {
    __half ha = __float2half_rn(a), hb = __float2half_rn(b);
    __half la = __float2half_rn(a - __half2float(ha));
    __half lb = __float2half_rn(b - __half2float(hb));
    hi = ((uint32_t)__half_as_ushort(hb) << 16) | __half_as_ushort(ha);
    lo = ((uint32_t)__half_as_ushort(lb) << 16) | __half_as_ushort(la);
}
__device__ __forceinline__ void split_f16x4(float4 v, uint2& ph, uint2& pl) {
    split2(v.x, v.y, ph.x, pl.x);
    split2(v.z, v.w, ph.y, pl.y);
}

// ---------------------------------------------------------------------------
// conversion kernels
// ---------------------------------------------------------------------------
__global__ void __launch_bounds__(256) split_w8_kernel(
    const float4* __restrict__ w0, const float4* __restrict__ w1,
    const float4* __restrict__ w2, const float4* __restrict__ w3,
    const float4* __restrict__ w4, const float4* __restrict__ w5,
    const float4* __restrict__ w6, const float4* __restrict__ w7,
    uint2* __restrict__ hi, uint2* __restrict__ lo, int n4)
{
    int i = blockIdx.x * 256 + threadIdx.x;
    int z = blockIdx.y;
    if (i < n4) {
        const float4* src = (z == 0) ? w0 : (z == 1) ? w1 : (z == 2) ? w2 : (z == 3) ? w3
                          : (z == 4) ? w4 : (z == 5) ? w5 : (z == 6) ? w6 : w7;
        uint2 ph, pl;
        split_f16x4(src[i], ph, pl);
        hi[(size_t)z * n4 + i] = ph;
        lo[(size_t)z * n4 + i] = pl;
    }
}

// fp32 [BB][rpb][DIM] -> fp16 hi only, joint rows (b*SEQ + dst_off + s)
__global__ void __launch_bounds__(256) conv_hi_kernel(
    const float4* __restrict__ src, uint2* __restrict__ hi, int rpb, int dst_off)
{
    int i = blockIdx.x * 256 + threadIdx.x;
    int n4 = BB * rpb * (DIM / 4);
    if (i < n4) {
        int q = i % (DIM / 4);
        int row = i / (DIM / 4);
        int b = row / rpb, s = row % rpb;
        float4 v = src[i];
        uint2 ph;
        ph.x = pack_h2(v.x, v.y);
        ph.y = pack_h2(v.z, v.w);
        hi[(b * SEQ + dst_off + s) * (DIM / 4) + q] = ph;
    }
}

// ===========================================================================
// fp16 2-pass GEMM, tile 128x128 (R7-proven config): C = A @ W + bias.
// A hi fp16, W hi/lo fp16. Warps 2M x 4N (64 rows x 32 cols). KC=32, 4-stage.
// Epilogue modes per z:
//   Hz==null            -> fp32 C output (out projections)
//   Hz!=null, Gz==null  -> fp16 hi/lo split output (V path)
//   Hz!=null, Gz!=null  -> fused RMS-norm + RoPE + hi/lo split (Q/K paths;
//                          tile = exactly one head since HD == tile width)
// ===========================================================================
#define KC 32
#define CHUNKS (DIM / KC)                  // 96
#define A_ST2 80
#define B_ST2 272
#define A_TILE_B (128 * A_ST2)              // 10240
#define B_TILE_B (32 * B_ST2)               // 8704
#define OFF_BHI A_TILE_B
#define OFF_BLO (A_TILE_B + B_TILE_B)
#define STAGE_B (A_TILE_B + 2 * B_TILE_B)   // 27648
#define NSTAGE 4
#define GEMM_SMEM_BYTES (NSTAGE * STAGE_B)  // 110592

__global__ void __launch_bounds__(256) mma_gemm_kernel(
    const __half* __restrict__ Ahi_g, int a_off, int rpb,
    const __half* __restrict__ Whi_base, const __half* __restrict__ Wlo_base,
    int w0, int w1, int w2,
    const float* bias0, const float* bias1, const float* bias2,
    float* C0, float* C1, float* C2,
    __half* H0, __half* L0, __half* H1, __half* L1, __half* H2, __half* L2,
    const float* G0, const float* G1,
    const float* __restrict__ cosb, const float* __restrict__ sinb,
    int c_seq, int c_off)
{
    extern __shared__ __align__(128) char smem[];
    const uint32_t sbase = smem_u32(smem);
    const int tid = threadIdx.x;
    const int wid = tid >> 5, lane = tid & 31;
    const int warp_m = wid >> 2;           // 2 groups of 64 rows
    const int warp_n = wid & 3;            // 4 groups of 32 cols
    const int z = blockIdx.z;

    const int widx = (z == 0) ? w0 : ((z == 1) ? w1 : w2);
    const float* bias = (z == 0) ? bias0 : ((z == 1) ? bias1 : bias2);
    float* C_base = (z == 0) ? C0 : ((z == 1) ? C1 : C2);
    __half* Hz = (z == 0) ? H0 : ((z == 1) ? H1 : H2);
    __half* Lz = (z == 0) ? L0 : ((z == 1) ? L1 : L2);
    const float* Gz = (z == 0) ? G0 : ((z == 1) ? G1 : nullptr);
    const __half* Whi = Whi_base + (size_t)widx * DIM * DIM;
    const __half* Wlo = Wlo_base + (size_t)widx * DIM * DIM;

    const int row0 = blockIdx.y * 128;
    const int col0 = blockIdx.x * 128;
    const int b  = row0 / rpb;
    const int s0r = row0 % rpb;
    const __half* Ahi = Ahi_g + (size_t)(b * SEQ + a_off + s0r) * DIM;
    const size_t crow0 = (size_t)(b * c_seq + c_off + s0r);
    float* C = C_base + crow0 * DIM;

#define ISSUE(c) do { \
    const int k0 = (c) * KC; \
    const uint32_t stb = sbase + ((c) % NSTAGE) * STAGE_B; \
    _Pragma("unroll") \
    for (int i = 0; i < 2; i++) { \
        int f = tid + i * 256; \
        uint32_t d = stb + (uint32_t)(f >> 2) * A_ST2 + (f & 3) * 16; \
        size_t so = (size_t)(f >> 2) * DIM + k0 + ((f & 3) << 3); \
        CPA16(d, (const void*)(Ahi + so)); \
        uint32_t db = stb + OFF_BHI + (uint32_t)(f >> 4) * B_ST2 + (f & 15) * 16; \
        size_t sb2 = (size_t)(k0 + (f >> 4)) * DIM + col0 + ((f & 15) << 3); \
        CPA16(db, (const void*)(Whi + sb2)); \
        CPA16(db + B_TILE_B, (const void*)(Wlo + sb2)); \
    } \
    CP_COMMIT(); \
} while (0)

    float acc[4][4][4];
#pragma unroll
    for (int i = 0; i < 4; i++)
#pragma unroll
        for (int j = 0; j < 4; j++)
#pragma unroll
            for (int k = 0; k < 4; k++) acc[i][j][k] = 0.f;

    const uint32_t a_row = (uint32_t)(warp_m * 64 + (lane & 15));
    const uint32_t a_sel = (uint32_t)((lane >> 4) * 16);
    const uint32_t b_row = (uint32_t)(lane & 15);
    const uint32_t b_sel = (uint32_t)(warp_n * 64 + ((lane >> 4) * 16));

#define COMPUTE(sidx) do { \
    const uint32_t sb = sbase + (sidx) * STAGE_B; \
    _Pragma("unroll") \
    for (int ks = 0; ks < 2; ks++) { \
        uint32_t ah[4][4]; \
        _Pragma("unroll") \
        for (int mt = 0; mt < 4; mt++) { \
            uint32_t ad = sb + (a_row + mt * 16) * A_ST2 + ks * 32 + a_sel; \
            LDM4(ah[mt], ad); \
        } \
        _Pragma("unroll") \
        for (int ng = 0; ng < 2; ng++) { \
            uint32_t bh[4], bl[4]; \
            uint32_t bd = sb + OFF_BHI + (ks * 16 + b_row) * B_ST2 + b_sel + ng * 32; \
            LDM4T(bh, bd); \
            LDM4T(bl, bd + B_TILE_B); \
            _Pragma("unroll") \
            for (int mt = 0; mt < 4; mt++) { \
                MMA_F16(acc[mt][ng * 2 + 0], ah[mt], bh[0], bh[1]); \
                MMA_F16(acc[mt][ng * 2 + 0], ah[mt], bl[0], bl[1]); \
                MMA_F16(acc[mt][ng * 2 + 1], ah[mt], bh[2], bh[3]); \
                MMA_F16(acc[mt][ng * 2 + 1], ah[mt], bl[2], bl[3]); \
            } \
        } \
    } \
} while (0)

    ISSUE(0); ISSUE(1); ISSUE(2);
    for (int c = 0; c < CHUNKS; c++) {
        if (c < CHUNKS - 2) { CP_WAIT(2); }
        else if (c == CHUNKS - 2) { CP_WAIT(1); }
        else { CP_WAIT(0); }
        __syncthreads();
        if (c + 3 < CHUNKS) ISSUE(c + 3);
        COMPUTE(c % NSTAGE);
    }

    // ---------------- epilogue ----------------
    const int m_base = warp_m * 64;
    const int n_loc  = warp_n * 32;         // col offset within the 128-wide tile

    // add bias into acc
#pragma unroll
    for (int mt = 0; mt < 4; mt++)
#pragma unroll
        for (int nt = 0; nt < 4; nt++) {
            int cc = col0 + n_loc + nt * 8 + ((lane & 3) << 1);
            float b0 = bias[cc], b1 = bias[cc + 1];
            acc[mt][nt][0] += b0; acc[mt][nt][1] += b1;
            acc[mt][nt][2] += b0; acc[mt][nt][3] += b1;
        }

    if (Hz == nullptr) {
        // fp32 output (out projections)
#pragma unroll
        for (int mt = 0; mt < 4; mt++)
#pragma unroll
            for (int nt = 0; nt < 4; nt++) {
                int r  = m_base + mt * 16 + (lane >> 2);
                int cc = col0 + n_loc + nt * 8 + ((lane & 3) << 1);
                *(float2*)(C + (size_t)r * DIM + cc) =
                    make_float2(acc[mt][nt][0], acc[mt][nt][1]);
                *(float2*)(C + (size_t)(r + 8) * DIM + cc) =
                    make_float2(acc[mt][nt][2], acc[mt][nt][3]);
            }
    } else if (Gz == nullptr) {
        // V path: straight hi/lo split
#pragma unroll
        for (int mt = 0; mt < 4; mt++)
#pragma unroll
            for (int nt = 0; nt < 4; nt++) {
                int r  = m_base + mt * 16 + (lane >> 2);
                int cc = col0 + n_loc + nt * 8 + ((lane & 3) << 1);
                uint32_t h0, l0, h1, l1;
                split2(acc[mt][nt][0], acc[mt][nt][1], h0, l0);
                split2(acc[mt][nt][2], acc[mt][nt][3], h1, l1);
                *(uint32_t*)(Hz + (crow0 + r) * DIM + cc) = h0;
                *(uint32_t*)(Lz + (crow0 + r) * DIM + cc) = l0;
                *(uint32_t*)(Hz + (crow0 + r + 8) * DIM + cc) = h1;
                *(uint32_t*)(Lz + (crow0 + r + 8) * DIM + cc) = l1;
            }
    } else {
        // Q/K path: RMS-norm over the 128-col head + RoPE + split.
        __syncthreads();                     // pipeline smem dead; reuse for reduce
        float* red = (float*)smem;           // [128][4]
        float ss[4][2];
#pragma unroll
        for (int mt = 0; mt < 4; mt++) {
            float p0 = 0.f, p1 = 0.f;
#pragma unroll
            for (int nt = 0; nt < 4; nt++) {
                p0 += acc[mt][nt][0] * acc[mt][nt][0] + acc[mt][nt][1] * acc[mt][nt][1];
                p1 += acc[mt][nt][2] * acc[mt][nt][2] + acc[mt][nt][3] * acc[mt][nt][3];
            }
            // sum over the 4 lanes sharing this row (lane&3 = 0..3)
            p0 += __shfl_xor_sync(0xffffffffu, p0, 1);
            p0 += __shfl_xor_sync(0xffffffffu, p0, 2);
            p1 += __shfl_xor_sync(0xffffffffu, p1, 1);
            p1 += __shfl_xor_sync(0xffffffffu, p1, 2);
            ss[mt][0] = p0; ss[mt][1] = p1;
        }
        if ((lane & 3) == 0) {
#pragma unroll
            for (int mt = 0; mt < 4; mt++) {
                int rl = m_base + mt * 16 + (lane >> 2);
                red[rl * 4 + warp_n] = ss[mt][0];
                red[(rl + 8) * 4 + warp_n] = ss[mt][1];
            }
        }
        __syncthreads();
#pragma unroll
        for (int mt = 0; mt < 4; mt++) {
            int rl = m_base + mt * 16 + (lane >> 2);
            float sm0 = red[rl * 4 + 0] + red[rl * 4 + 1] + red[rl * 4 + 2] + red[rl * 4 + 3];
            float sm1 = red[(rl + 8) * 4 + 0] + red[(rl + 8) * 4 + 1]
                      + red[(rl + 8) * 4 + 2] + red[(rl + 8) * 4 + 3];
            float scl0 = rsqrtf(sm0 * (1.0f / HD) + EPSF);
            float scl1 = rsqrtf(sm1 * (1.0f / HD) + EPSF);
            int sp0 = c_off + s0r + rl;        // joint sequence position
            int sp1 = sp0 + 8;
#pragma unroll
            for (int nt = 0; nt < 4; nt++) {
                int d  = n_loc + nt * 8 + ((lane & 3) << 1);   // 0..126 even
                int cc = col0 + d;
                float gd0 = Gz[d], gd1 = Gz[d + 1];
                float c0 = cosb[sp0 * (HD / 2) + (d >> 1)];
                float n0 = sinb[sp0 * (HD / 2) + (d >> 1)];
                float c1 = cosb[sp1 * (HD / 2) + (d >> 1)];
                float n1 = sinb[sp1 * (HD / 2) + (d >> 1)];
                float x0 = acc[mt][nt][0] * scl0 * gd0;
                float x1 = acc[mt][nt][1] * scl0 * gd1;
                float y0 = acc[mt][nt][2] * scl1 * gd0;
                float y1 = acc[mt][nt][3] * scl1 * gd1;
                uint32_t h0, l0, h1, l1;
                split2(x0 * c0 - x1 * n0, x0 * n0 + x1 * c0, h0, l0);
                split2(y0 * c1 - y1 * n1, y0 * n1 + y1 * c1, h1, l1);
                *(uint32_t*)(Hz + (crow0 + rl) * DIM + cc) = h0;
                *(uint32_t*)(Lz + (crow0 + rl) * DIM + cc) = l0;
                *(uint32_t*)(Hz + (crow0 + rl + 8) * DIM + cc) = h1;
                *(uint32_t*)(Lz + (crow0 + rl + 8) * DIM + cc) = l1;
            }
        }
    }
#undef ISSUE
#undef COMPUTE
}

// ===========================================================================
// Flash attention via mma.sync fp16 (R7-proven).
// QK^T 3-pass (hi/lo), PV 2-pass (P hi). Output hi-only to Xhi.
// ===========================================================================
#define FROW_B 272
#define FK_HI 0
#define FK_LO (32 * FROW_B)
#define FV_HI (2 * 32 * FROW_B)
#define FV_LO (3 * 32 * FROW_B)
#define FSTAGE_B (4 * 32 * FROW_B)
#define FNSTAGE 3
#define FLASH_SMEM_BYTES (FNSTAGE * FSTAGE_B)
#define FITERS (SEQ / 32)

__global__ void __launch_bounds__(256) flash_mma_kernel(
    const __half* __restrict__ Qhi_g, const __half* __restrict__ Qlo_g,
    const __half* __restrict__ Khi_g, const __half* __restrict__ Klo_g,
    const __half* __restrict__ Vhi_g, const __half* __restrict__ Vlo_g,
    __half* __restrict__ Ohi)
{
    extern __shared__ __align__(128) char smem[];
    const uint32_t sbase = smem_u32(smem);
    const int tid = threadIdx.x;
    const int wq = tid >> 5, lane = tid & 31;
    const int q0 = blockIdx.x * 128;
    const int bh = blockIdx.y;
    const int b = bh / HEADS, h = bh % HEADS;
    const size_t hoff = (size_t)h * HD;

    {
#pragma unroll
        for (int i = 0; i < 8; i++) {
            int f = tid + i * 256;
            int r = f >> 4, c = f & 15;
            uint32_t d = sbase + (uint32_t)r * FROW_B + c * 16;
            size_t so = (size_t)(b * SEQ + q0 + r) * DIM + hoff + c * 8;
            CPA16(d, (const void*)(Qhi_g + so));
            CPA16(d + 34816, (const void*)(Qlo_g + so));
        }
        CP_COMMIT();
        CP_WAIT(0);
        __syncthreads();
    }
    uint32_t qh[8][4], ql[8][4];
    {
        const uint32_t qrow = (uint32_t)(wq * 16 + (lane & 15));
        const uint32_t qc8  = (uint32_t)((lane >> 4) * 16);
#pragma unroll
        for (int ks = 0; ks < 8; ks++) {
            uint32_t ad = sbase + qrow * FROW_B + ks * 32 + qc8;
            LDM4(qh[ks], ad);
            LDM4(ql[ks], ad + 34816);
        }
    }
    __syncthreads();

#define FISSUE(kt) do { \
    const int k0 = (kt) * 32; \
    const uint32_t stb = sbase + ((kt) % FNSTAGE) * FSTAGE_B; \
    _Pragma("unroll") \
    for (int i = 0; i < 2; i++) { \
        int f = tid + i * 256; \
        int r = f >> 4, c = f & 15; \
        uint32_t d = stb + (uint32_t)r * FROW_B + c * 16; \
        size_t so = (size_t)(b * SEQ + k0 + r) * DIM + hoff + c * 8; \
        CPA16(d + FK_HI, (const void*)(Khi_g + so)); \
        CPA16(d + FK_LO, (const void*)(Klo_g + so)); \
        CPA16(d + FV_HI, (const void*)(Vhi_g + so)); \
        CPA16(d + FV_LO, (const void*)(Vlo_g + so)); \
    } \
    CP_COMMIT(); \
} while (0)

    float acc[16][4];
#pragma unroll
    for (int i = 0; i < 16; i++)
#pragma unroll
        for (int j = 0; j < 4; j++) acc[i][j] = 0.f;
    float m0 = -1e30f, m1 = -1e30f, l0 = 0.f, l1 = 0.f;

    const uint32_t krow = (uint32_t)(lane & 15);
    const uint32_t kc8  = (uint32_t)((lane >> 4) * 16);

    FISSUE(0); FISSUE(1);
    for (int kt = 0; kt < FITERS; kt++) {
        if (kt == FITERS - 1) { CP_WAIT(0); } else { CP_WAIT(1); }
        __syncthreads();
        if (kt + 2 < FITERS) FISSUE(kt + 2);
        const uint32_t stb = sbase + (kt % FNSTAGE) * FSTAGE_B;

        float s[4][4];
#pragma unroll
        for (int i = 0; i < 4; i++)
#pragma unroll
            for (int j = 0; j < 4; j++) s[i][j] = 0.f;
#pragma unroll
        for (int ks = 0; ks < 8; ks++) {
#pragma unroll
            for (int half = 0; half < 2; half++) {
                uint32_t kbh[4], kbl[4];
                uint32_t kd = stb + FK_HI + (half * 16 + krow) * FROW_B + ks * 32 + kc8;
                LDM4(kbh, kd);
                LDM4(kbl, kd + FK_LO);
                MMA_F16(s[2 * half + 0], qh[ks], kbh[0], kbh[2]);
                MMA_F16(s[2 * half + 0], qh[ks], kbl[0], kbl[2]);
                MMA_F16(s[2 * half + 0], ql[ks], kbh[0], kbh[2]);
                MMA_F16(s[2 * half + 1], qh[ks], kbh[1], kbh[3]);
                MMA_F16(s[2 * half + 1], qh[ks], kbl[1], kbl[3]);
                MMA_F16(s[2 * half + 1], ql[ks], kbh[1], kbh[3]);
            }
        }
#pragma unroll
        for (int i = 0; i < 4; i++)
#pragma unroll
            for (int j = 0; j < 4; j++) s[i][j] *= SCALEF;

        float mx0 = fmaxf(fmaxf(s[0][0], s[0][1]), fmaxf(s[1][0], s[1][1]));
        mx0 = fmaxf(mx0, fmaxf(fmaxf(s[2][0], s[2][1]), fmaxf(s[3][0], s[3][1])));
        float mx1 = fmaxf(fmaxf(s[0][2], s[0][3]), fmaxf(s[1][2], s[1][3]));
        mx1 = fmaxf(mx1, fmaxf(fmaxf(s[2][2], s[2][3]), fmaxf(s[3][2], s[3][3])));
#pragma unroll
        for (int o = 1; o <= 2; o <<= 1) {
            mx0 = fmaxf(mx0, __shfl_xor_sync(0xffffffffu, mx0, o));
            mx1 = fmaxf(mx1, __shfl_xor_sync(0xffffffffu, mx1, o));
        }
        float mn0 = fmaxf(m0, mx0), mn1 = fmaxf(m1, mx1);
        float f0 = __expf(m0 - mn0), f1 = __expf(m1 - mn1);
        m0 = mn0; m1 = mn1;
        float rs0 = 0.f, rs1 = 0.f;
#pragma unroll
        for (int nt = 0; nt < 4; nt++) {
            s[nt][0] = __expf(s[nt][0] - mn0);
            s[nt][1] = __expf(s[nt][1] - mn0);
            s[nt][2] = __expf(s[nt][2] - mn1);
            s[nt][3] = __expf(s[nt][3] - mn1);
            rs0 += s[nt][0] + s[nt][1];
            rs1 += s[nt][2] + s[nt][3];
        }
#pragma unroll
        for (int o = 1; o <= 2; o <<= 1) {
            rs0 += __shfl_xor_sync(0xffffffffu, rs0, o);
            rs1 += __shfl_xor_sync(0xffffffffu, rs1, o);
        }
        l0 = l0 * f0 + rs0;
        l1 = l1 * f1 + rs1;
#pragma unroll
        for (int i = 0; i < 16; i++) {
            acc[i][0] *= f0; acc[i][1] *= f0;
            acc[i][2] *= f1; acc[i][3] *= f1;
        }

        uint32_t ph[2][4];
#pragma unroll
        for (int k2 = 0; k2 < 2; k2++) {
            ph[k2][0] = pack_h2(s[2 * k2][0],     s[2 * k2][1]);
            ph[k2][1] = pack_h2(s[2 * k2][2],     s[2 * k2][3]);
            ph[k2][2] = pack_h2(s[2 * k2 + 1][0], s[2 * k2 + 1][1]);
            ph[k2][3] = pack_h2(s[2 * k2 + 1][2], s[2 * k2 + 1][3]);
        }
#pragma unroll
        for (int ng = 0; ng < 8; ng++) {
#pragma unroll
            for (int k2 = 0; k2 < 2; k2++) {
                uint32_t vbh[4], vbl[4];
                uint32_t vd = stb + FV_HI + (k2 * 16 + krow) * FROW_B + ng * 32 + kc8;
                LDM4T(vbh, vd);
                LDM4T(vbl, vd + (FV_LO - FV_HI));
                MMA_F16(acc[2 * ng + 0], ph[k2], vbh[0], vbh[1]);
                MMA_F16(acc[2 * ng + 0], ph[k2], vbl[0], vbl[1]);
                MMA_F16(acc[2 * ng + 1], ph[k2], vbh[2], vbh[3]);
                MMA_F16(acc[2 * ng + 1], ph[k2], vbl[2], vbl[3]);
            }
        }
    }

    float inv0 = 1.0f / l0, inv1 = 1.0f / l1;
    const int r0g = b * SEQ + q0 + wq * 16 + (lane >> 2);
#pragma unroll
    for (int nt = 0; nt < 16; nt++) {
        int cc = (int)hoff + nt * 8 + ((lane & 3) << 1);
        *(uint32_t*)(Ohi + (size_t)r0g * DIM + cc) =
            pack_h2(acc[nt][0] * inv0, acc[nt][1] * inv0);
        *(uint32_t*)(Ohi + (size_t)(r0g + 8) * DIM + cc) =
            pack_h2(acc[nt][2] * inv1, acc[nt][3] * inv1);
    }
#undef FISSUE
}

// ---------------------------------------------------------------------------
extern "C" void kernel_launch(void* const* d_in, const int* in_sizes, int n_in,
                              void* d_out, int out_size)
{
    (void)in_sizes; (void)n_in; (void)out_size;
    const float* x     = (const float*)d_in[0];
    const float* ctx   = (const float*)d_in[1];
    const float* cosb  = (const float*)d_in[2];
    const float* sinb  = (const float*)d_in[3];
    const float* bq    = (const float*)d_in[5];
    const float* bk    = (const float*)d_in[7];
    const float* bv    = (const float*)d_in[9];
    const float* bqc   = (const float*)d_in[11];
    const float* bkc   = (const float*)d_in[13];
    const float* bvc   = (const float*)d_in[15];
    const float* b_out = (const float*)d_in[17];
    const float* b_add = (const float*)d_in[19];
    const float* g_q   = (const float*)d_in[20];
    const float* g_k   = (const float*)d_in[21];
    const float* g_qc  = (const float*)d_in[22];
    const float* g_kc  = (const float*)d_in[23];
    float* out = (float*)d_out;

    __half *Whi, *Wlo, *Xhi, *Qhi, *Qlo, *Khi, *Klo, *Vhi, *Vlo;
    cudaGetSymbolAddress((void**)&Whi, g_Whi);
    cudaGetSymbolAddress((void**)&Wlo, g_Wlo);
    cudaGetSymbolAddress((void**)&Xhi, g_Xhi);
    cudaGetSymbolAddress((void**)&Qhi, g_Qhi);
    cudaGetSymbolAddress((void**)&Qlo, g_Qlo);
    cudaGetSymbolAddress((void**)&Khi, g_Khi);
    cudaGetSymbolAddress((void**)&Klo, g_Klo);
    cudaGetSymbolAddress((void**)&Vhi, g_Vhi);
    cudaGetSymbolAddress((void**)&Vlo, g_Vlo);

    cudaFuncSetAttribute(mma_gemm_kernel,
                         cudaFuncAttributeMaxDynamicSharedMemorySize, GEMM_SMEM_BYTES);
    cudaFuncSetAttribute(flash_mma_kernel,
                         cudaFuncAttributeMaxDynamicSharedMemorySize, FLASH_SMEM_BYTES);

    const int WN4 = DIM * DIM / 4;

    // preconvert all 8 weights (fp16 hi/lo), one launch
    split_w8_kernel<<<dim3((WN4 + 255) / 256, 8), 256>>>(
        (const float4*)d_in[4],  (const float4*)d_in[6],  (const float4*)d_in[8],
        (const float4*)d_in[10], (const float4*)d_in[12], (const float4*)d_in[14],
        (const float4*)d_in[16], (const float4*)d_in[18],
        (uint2*)Whi, (uint2*)Wlo, WN4);

    // preconvert activations (fp16 hi only) into joint layout
    conv_hi_kernel<<<(BB * S_TXT * (DIM / 4) + 255) / 256, 256>>>(
        (const float4*)ctx, (uint2*)Xhi, S_TXT, 0);
    conv_hi_kernel<<<(BB * S_IMG * (DIM / 4) + 255) / 256, 256>>>(
        (const float4*)x, (uint2*)Xhi, S_IMG, S_TXT);

    // QKV projections, merged z=3. Q/K epilogue does bias+RMS+RoPE+split;
    // V epilogue does bias+split. No fp32 intermediates, no rmsrope kernel.
    dim3 gImg3(DIM / 128, (BB * S_IMG) / 128, 3);
    dim3 gTxt3(DIM / 128, (BB * S_TXT) / 128, 3);
    mma_gemm_kernel<<<gImg3, 256, GEMM_SMEM_BYTES>>>(Xhi, S_TXT, S_IMG,
        Whi, Wlo, 0, 1, 2, bq, bk, bv,
        nullptr, nullptr, nullptr,
        Qhi, Qlo, Khi, Klo, Vhi, Vlo,
        g_q, g_k, cosb, sinb, SEQ, S_TXT);
    mma_gemm_kernel<<<gTxt3, 256, GEMM_SMEM_BYTES>>>(Xhi, 0, S_TXT,
        Whi, Wlo, 3, 4, 5, bqc, bkc, bvc,
        nullptr, nullptr, nullptr,
        Qhi, Qlo, Khi, Klo, Vhi, Vlo,
        g_qc, g_kc, cosb, sinb, SEQ, 0);

    // Flash attention (writes fp16 hi output into Xhi)
    flash_mma_kernel<<<dim3(SEQ / 128, BB * HEADS), 256, FLASH_SMEM_BYTES>>>(
        Qhi, Qlo, Khi, Klo, Vhi, Vlo, Xhi);

    // output projections (fp32 out)
    dim3 gTxt(DIM / 128, (BB * S_TXT) / 128, 1);
    dim3 gImg(DIM / 128, (BB * S_IMG) / 128, 1);
    mma_gemm_kernel<<<gTxt, 256, GEMM_SMEM_BYTES>>>(Xhi, 0, S_TXT,
        Whi, Wlo, 7, 7, 7, b_add, b_add, b_add, out, out, out,
        nullptr, nullptr, nullptr, nullptr, nullptr, nullptr,
        nullptr, nullptr, cosb, sinb, S_TXT, 0);
    mma_gemm_kernel<<<gImg, 256, GEMM_SMEM_BYTES>>>(Xhi, S_TXT, S_IMG,
        Whi, Wlo, 6, 6, 6, b_out, b_out, b_out,
        out + (size_t)BB * S_TXT * DIM, out + (size_t)BB * S_TXT * DIM,
        out + (size_t)BB * S_TXT * DIM,
        nullptr, nullptr, nullptr, nullptr, nullptr, nullptr,
        nullptr, nullptr, cosb, sinb, S_IMG, 0);
}

// round 11
// speedup vs baseline: 1.6409x; 1.4730x over previous
#include <cuda_runtime.h>
#include <cuda_fp16.h>
#include <cstdint>
#include <math.h>

#define BB 2
#define S_IMG 1024
#define S_TXT 512
#define SEQ 1536
#define DIM 3072
#define HEADS 24
#define HD 128
#define EPSF 1e-6f
#define SCALEF 0.08838834764831845f

// Scratch (device globals -- no allocation allowed)
__device__ __half g_Whi[8 * DIM * DIM];
__device__ __half g_Xhi[BB * SEQ * DIM];
__device__ __half g_Qhi[BB * SEQ * DIM];
__device__ __half g_Qlo[BB * SEQ * DIM];
__device__ __half g_Khi[BB * SEQ * DIM];
__device__ __half g_Klo[BB * SEQ * DIM];
__device__ __half g_Vhi[BB * SEQ * DIM];
__device__ __half g_Vlo[BB * SEQ * DIM];

// ===========================================================================
// helpers
// ===========================================================================
__device__ __forceinline__ uint32_t smem_u32(const void* p) {
    uint32_t a;
    asm("{ .reg .u64 t; cvta.to.shared.u64 t, %1; cvt.u32.u64 %0, t; }"
        : "=r"(a) : "l"(p));
    return a;
}
#define LDM4(r, a) \
    asm volatile("ldmatrix.sync.aligned.m8n8.x4.shared.b16 {%0,%1,%2,%3}, [%4];" \
        : "=r"((r)[0]), "=r"((r)[1]), "=r"((r)[2]), "=r"((r)[3]) : "r"(a))
#define LDM4T(r, a) \
    asm volatile("ldmatrix.sync.aligned.m8n8.x4.trans.shared.b16 {%0,%1,%2,%3}, [%4];" \
        : "=r"((r)[0]), "=r"((r)[1]), "=r"((r)[2]), "=r"((r)[3]) : "r"(a))
#define MMA_F16(d, a, b0, b1) \
    asm volatile("mma.sync.aligned.m16n8k16.row.col.f32.f16.f16.f32 " \
        "{%0,%1,%2,%3}, {%4,%5,%6,%7}, {%8,%9}, {%0,%1,%2,%3};" \
        : "+f"((d)[0]), "+f"((d)[1]), "+f"((d)[2]), "+f"((d)[3]) \
        : "r"((a)[0]), "r"((a)[1]), "r"((a)[2]), "r"((a)[3]), "r"(b0), "r"(b1))
#define CPA16(dst, src) \
    asm volatile("cp.async.cg.shared.global [%0], [%1], 16;" :: "r"(dst), "l"(src))
#define CP_COMMIT() asm volatile("cp.async.commit_group;" ::: "memory")
#define CP_WAIT(n)  asm volatile("cp.async.wait_group %0;" :: "n"(n) : "memory")

__device__ __forceinline__ uint32_t pack_h2(float a, float b) {
    __half2 h = __floats2half2_rn(a, b);
    return *(uint32_t*)&h;
}
__device__ __forceinline__ void split2(float a, float b, uint32_t& hi, uint32_t& lo) {
    __half ha = __float2half_rn(a), hb = __float2half_rn(b);
    __half la = __float2half_rn(a - __half2float(ha));
    __half lb = __float2half_rn(b - __half2float(hb));
    hi = ((uint32_t)__half_as_ushort(hb) << 16) | __half_as_ushort(ha);
    lo = ((uint32_t)__half_as_ushort(lb) << 16) | __half_as_ushort(la);
}

// ---------------------------------------------------------------------------
// conversion kernels
// ---------------------------------------------------------------------------
// merged weight convert (hi only): grid.y selects the weight matrix
__global__ void __launch_bounds__(256) conv_w8_kernel(
    const float4* __restrict__ w0, const float4* __restrict__ w1,
    const float4* __restrict__ w2, const float4* __restrict__ w3,
    const float4* __restrict__ w4, const float4* __restrict__ w5,
    const float4* __restrict__ w6, const float4* __restrict__ w7,
    uint2* __restrict__ hi, int n4)
{
    int i = blockIdx.x * 256 + threadIdx.x;
    int z = blockIdx.y;
    if (i < n4) {
        const float4* src = (z == 0) ? w0 : (z == 1) ? w1 : (z == 2) ? w2 : (z == 3) ? w3
                          : (z == 4) ? w4 : (z == 5) ? w5 : (z == 6) ? w6 : w7;
        float4 v = src[i];
        uint2 ph;
        ph.x = pack_h2(v.x, v.y);
        ph.y = pack_h2(v.z, v.w);
        hi[(size_t)z * n4 + i] = ph;
    }
}

// fp32 [BB][rpb][DIM] -> fp16 hi only, joint rows (b*SEQ + dst_off + s)
__global__ void __launch_bounds__(256) conv_hi_kernel(
    const float4* __restrict__ src, uint2* __restrict__ hi, int rpb, int dst_off)
{
    int i = blockIdx.x * 256 + threadIdx.x;
    int n4 = BB * rpb * (DIM / 4);
    if (i < n4) {
        int q = i % (DIM / 4);
        int row = i / (DIM / 4);
        int b = row / rpb, s = row % rpb;
        float4 v = src[i];
        uint2 ph;
        ph.x = pack_h2(v.x, v.y);
        ph.y = pack_h2(v.z, v.w);
        hi[(b * SEQ + dst_off + s) * (DIM / 4) + q] = ph;
    }
}

// ===========================================================================
// fp16 1-pass GEMM, tile 128x128: C = A @ W + bias; A hi fp16, W hi fp16.
// Warps 2M x 4N (64 rows x 32 cols). KC=32, 5-stage cp.async pipeline.
// mode 0 (QKV): tile txt/img-ness picks weight variant; z in {0,1,2} = Q/K/V.
//   z<2: fused bias + RMS-norm + RoPE + hi/lo split (tile == one head).
//   z=2: bias + hi/lo split (V).
// mode 1 (out-proj): picks w_out/w_add per tile, fp32 out with row remap.
// ===========================================================================
#define KC 32
#define CHUNKS (DIM / KC)                  // 96
#define A_ST2 80
#define B_ST2 272
#define A_TILE_B (128 * A_ST2)              // 10240
#define B_TILE_B (32 * B_ST2)               // 8704
#define OFF_BHI A_TILE_B
#define STAGE_B (A_TILE_B + B_TILE_B)       // 18944
#define NSTAGE 5
#define GEMM_SMEM_BYTES (NSTAGE * STAGE_B)  // 94720

__global__ void __launch_bounds__(256) mma_gemm_kernel(
    int mode,
    const __half* __restrict__ Xg,          // joint fp16 activations
    const __half* __restrict__ Whi_base,
    const float* bq, const float* bk, const float* bv,
    const float* bqc, const float* bkc, const float* bvc,
    const float* b_out, const float* b_add,
    const float* g_q, const float* g_k, const float* g_qc, const float* g_kc,
    const float* __restrict__ cosb, const float* __restrict__ sinb,
    __half* Qhi, __half* Qlo, __half* Khi, __half* Klo, __half* Vhi, __half* Vlo,
    float* out)
{
    extern __shared__ __align__(128) char smem[];
    const uint32_t sbase = smem_u32(smem);
    const int tid = threadIdx.x;
    const int wid = tid >> 5, lane = tid & 31;
    const int warp_m = wid >> 2;           // 2 groups of 64 rows
    const int warp_n = wid & 3;            // 4 groups of 32 cols
    const int z = blockIdx.z;

    const int row0 = blockIdx.y * 128;     // joint row (b*SEQ + sj)
    const int col0 = blockIdx.x * 128;
    const int b  = row0 / SEQ;
    const int sj = row0 % SEQ;
    const bool txt = (sj < S_TXT);

    int widx;
    const float* bias;
    __half *Hz = nullptr, *Lz = nullptr;
    const float* Gz = nullptr;
    float* C = nullptr;
    if (mode == 0) {
        widx = txt ? (3 + z) : z;
        bias = (z == 0) ? (txt ? bqc : bq) : (z == 1) ? (txt ? bkc : bk) : (txt ? bvc : bv);
        Hz = (z == 0) ? Qhi : (z == 1) ? Khi : Vhi;
        Lz = (z == 0) ? Qlo : (z == 1) ? Klo : Vlo;
        Gz = (z == 0) ? (txt ? g_qc : g_q) : (z == 1) ? (txt ? g_kc : g_k) : nullptr;
    } else {
        widx = txt ? 7 : 6;
        bias = txt ? b_add : b_out;
        size_t crow = txt ? (size_t)(b * S_TXT + sj)
                          : (size_t)(BB * S_TXT + b * S_IMG + (sj - S_TXT));
        C = out + crow * DIM;
    }
    const __half* Whi = Whi_base + (size_t)widx * DIM * DIM;
    const __half* Ahi = Xg + (size_t)row0 * DIM;

#define ISSUE(c) do { \
    const int k0 = (c) * KC; \
    const uint32_t stb = sbase + ((c) % NSTAGE) * STAGE_B; \
    _Pragma("unroll") \
    for (int i = 0; i < 2; i++) { \
        int f = tid + i * 256; \
        uint32_t d = stb + (uint32_t)(f >> 2) * A_ST2 + (f & 3) * 16; \
        size_t so = (size_t)(f >> 2) * DIM + k0 + ((f & 3) << 3); \
        CPA16(d, (const void*)(Ahi + so)); \
        uint32_t db = stb + OFF_BHI + (uint32_t)(f >> 4) * B_ST2 + (f & 15) * 16; \
        size_t sb2 = (size_t)(k0 + (f >> 4)) * DIM + col0 + ((f & 15) << 3); \
        CPA16(db, (const void*)(Whi + sb2)); \
    } \
    CP_COMMIT(); \
} while (0)

    float acc[4][4][4];
#pragma unroll
    for (int i = 0; i < 4; i++)
#pragma unroll
        for (int j = 0; j < 4; j++)
#pragma unroll
            for (int k = 0; k < 4; k++) acc[i][j][k] = 0.f;

    const uint32_t a_row = (uint32_t)(warp_m * 64 + (lane & 15));
    const uint32_t a_sel = (uint32_t)((lane >> 4) * 16);
    const uint32_t b_row = (uint32_t)(lane & 15);
    const uint32_t b_sel = (uint32_t)(warp_n * 64 + ((lane >> 4) * 16));

#define COMPUTE(sidx) do { \
    const uint32_t sb = sbase + (sidx) * STAGE_B; \
    _Pragma("unroll") \
    for (int ks = 0; ks < 2; ks++) { \
        uint32_t ah[4][4]; \
        _Pragma("unroll") \
        for (int mt = 0; mt < 4; mt++) { \
            uint32_t ad = sb + (a_row + mt * 16) * A_ST2 + ks * 32 + a_sel; \
            LDM4(ah[mt], ad); \
        } \
        _Pragma("unroll") \
        for (int ng = 0; ng < 2; ng++) { \
            uint32_t bh[4]; \
            uint32_t bd = sb + OFF_BHI + (ks * 16 + b_row) * B_ST2 + b_sel + ng * 32; \
            LDM4T(bh, bd); \
            _Pragma("unroll") \
            for (int mt = 0; mt < 4; mt++) { \
                MMA_F16(acc[mt][ng * 2 + 0], ah[mt], bh[0], bh[1]); \
                MMA_F16(acc[mt][ng * 2 + 1], ah[mt], bh[2], bh[3]); \
            } \
        } \
    } \
} while (0)

    ISSUE(0); ISSUE(1); ISSUE(2); ISSUE(3);
    for (int c = 0; c < CHUNKS; c++) {
        if (c < CHUNKS - 3)      { CP_WAIT(3); }
        else if (c == CHUNKS - 3){ CP_WAIT(2); }
        else if (c == CHUNKS - 2){ CP_WAIT(1); }
        else                     { CP_WAIT(0); }
        __syncthreads();
        if (c + 4 < CHUNKS) ISSUE(c + 4);   // targets (c-1)%5, safe post-sync
        COMPUTE(c % NSTAGE);
    }

    // ---------------- epilogue ----------------
    const int m_base = warp_m * 64;
    const int n_loc  = warp_n * 32;

    // add bias
#pragma unroll
    for (int mt = 0; mt < 4; mt++)
#pragma unroll
        for (int nt = 0; nt < 4; nt++) {
            int cc = col0 + n_loc + nt * 8 + ((lane & 3) << 1);
            float b0 = bias[cc], b1 = bias[cc + 1];
            acc[mt][nt][0] += b0; acc[mt][nt][1] += b1;
            acc[mt][nt][2] += b0; acc[mt][nt][3] += b1;
        }

    if (mode == 1) {
        // fp32 output (out projections)
#pragma unroll
        for (int mt = 0; mt < 4; mt++)
#pragma unroll
            for (int nt = 0; nt < 4; nt++) {
                int r  = m_base + mt * 16 + (lane >> 2);
                int cc = col0 + n_loc + nt * 8 + ((lane & 3) << 1);
                *(float2*)(C + (size_t)r * DIM + cc) =
                    make_float2(acc[mt][nt][0], acc[mt][nt][1]);
                *(float2*)(C + (size_t)(r + 8) * DIM + cc) =
                    make_float2(acc[mt][nt][2], acc[mt][nt][3]);
            }
    } else if (Gz == nullptr) {
        // V path: hi/lo split at joint rows
#pragma unroll
        for (int mt = 0; mt < 4; mt++)
#pragma unroll
            for (int nt = 0; nt < 4; nt++) {
                int r  = m_base + mt * 16 + (lane >> 2);
                int cc = col0 + n_loc + nt * 8 + ((lane & 3) << 1);
                uint32_t h0, l0, h1, l1;
                split2(acc[mt][nt][0], acc[mt][nt][1], h0, l0);
                split2(acc[mt][nt][2], acc[mt][nt][3], h1, l1);
                *(uint32_t*)(Hz + (size_t)(row0 + r) * DIM + cc) = h0;
                *(uint32_t*)(Lz + (size_t)(row0 + r) * DIM + cc) = l0;
                *(uint32_t*)(Hz + (size_t)(row0 + r + 8) * DIM + cc) = h1;
                *(uint32_t*)(Lz + (size_t)(row0 + r + 8) * DIM + cc) = l1;
            }
    } else {
        // Q/K path: RMS-norm over the 128-col head + RoPE + split
        __syncthreads();
        float* red = (float*)smem;           // [128][4]
        float ss[4][2];
#pragma unroll
        for (int mt = 0; mt < 4; mt++) {
            float p0 = 0.f, p1 = 0.f;
#pragma unroll
            for (int nt = 0; nt < 4; nt++) {
                p0 += acc[mt][nt][0] * acc[mt][nt][0] + acc[mt][nt][1] * acc[mt][nt][1];
                p1 += acc[mt][nt][2] * acc[mt][nt][2] + acc[mt][nt][3] * acc[mt][nt][3];
            }
            p0 += __shfl_xor_sync(0xffffffffu, p0, 1);
            p0 += __shfl_xor_sync(0xffffffffu, p0, 2);
            p1 += __shfl_xor_sync(0xffffffffu, p1, 1);
            p1 += __shfl_xor_sync(0xffffffffu, p1, 2);
            ss[mt][0] = p0; ss[mt][1] = p1;
        }
        if ((lane & 3) == 0) {
#pragma unroll
            for (int mt = 0; mt < 4; mt++) {
                int rl = m_base + mt * 16 + (lane >> 2);
                red[rl * 4 + warp_n] = ss[mt][0];
                red[(rl + 8) * 4 + warp_n] = ss[mt][1];
            }
        }
        __syncthreads();
#pragma unroll
        for (int mt = 0; mt < 4; mt++) {
            int rl = m_base + mt * 16 + (lane >> 2);
            float sm0 = red[rl * 4 + 0] + red[rl * 4 + 1] + red[rl * 4 + 2] + red[rl * 4 + 3];
            float sm1 = red[(rl + 8) * 4 + 0] + red[(rl + 8) * 4 + 1]
                      + red[(rl + 8) * 4 + 2] + red[(rl + 8) * 4 + 3];
            float scl0 = rsqrtf(sm0 * (1.0f / HD) + EPSF);
            float scl1 = rsqrtf(sm1 * (1.0f / HD) + EPSF);
            int sp0 = sj + rl;
            int sp1 = sp0 + 8;
#pragma unroll
            for (int nt = 0; nt < 4; nt++) {
                int d  = n_loc + nt * 8 + ((lane & 3) << 1);
                int cc = col0 + d;
                float gd0 = Gz[d], gd1 = Gz[d + 1];
                float c0 = cosb[sp0 * (HD / 2) + (d >> 1)];
                float n0 = sinb[sp0 * (HD / 2) + (d >> 1)];
                float c1 = cosb[sp1 * (HD / 2) + (d >> 1)];
                float n1 = sinb[sp1 * (HD / 2) + (d >> 1)];
                float x0 = acc[mt][nt][0] * scl0 * gd0;
                float x1 = acc[mt][nt][1] * scl0 * gd1;
                float y0 = acc[mt][nt][2] * scl1 * gd0;
                float y1 = acc[mt][nt][3] * scl1 * gd1;
                uint32_t h0, l0, h1, l1;
                split2(x0 * c0 - x1 * n0, x0 * n0 + x1 * c0, h0, l0);
                split2(y0 * c1 - y1 * n1, y0 * n1 + y1 * c1, h1, l1);
                *(uint32_t*)(Hz + (size_t)(row0 + rl) * DIM + cc) = h0;
                *(uint32_t*)(Lz + (size_t)(row0 + rl) * DIM + cc) = l0;
                *(uint32_t*)(Hz + (size_t)(row0 + rl + 8) * DIM + cc) = h1;
                *(uint32_t*)(Lz + (size_t)(row0 + rl + 8) * DIM + cc) = l1;
            }
        }
    }
#undef ISSUE
#undef COMPUTE
}

// ===========================================================================
// Flash attention via mma.sync fp16 (R7/R10-proven, unchanged).
// QK^T 3-pass (hi/lo), PV 2-pass (P hi). Output hi-only to Xhi.
// ===========================================================================
#define FROW_B 272
#define FK_HI 0
#define FK_LO (32 * FROW_B)
#define FV_HI (2 * 32 * FROW_B)
#define FV_LO (3 * 32 * FROW_B)
#define FSTAGE_B (4 * 32 * FROW_B)
#define FNSTAGE 3
#define FLASH_SMEM_BYTES (FNSTAGE * FSTAGE_B)
#define FITERS (SEQ / 32)

__global__ void __launch_bounds__(256) flash_mma_kernel(
    const __half* __restrict__ Qhi_g, const __half* __restrict__ Qlo_g,
    const __half* __restrict__ Khi_g, const __half* __restrict__ Klo_g,
    const __half* __restrict__ Vhi_g, const __half* __restrict__ Vlo_g,
    __half* __restrict__ Ohi)
{
    extern __shared__ __align__(128) char smem[];
    const uint32_t sbase = smem_u32(smem);
    const int tid = threadIdx.x;
    const int wq = tid >> 5, lane = tid & 31;
    const int q0 = blockIdx.x * 128;
    const int bh = blockIdx.y;
    const int b = bh / HEADS, h = bh % HEADS;
    const size_t hoff = (size_t)h * HD;

    {
#pragma unroll
        for (int i = 0; i < 8; i++) {
            int f = tid + i * 256;
            int r = f >> 4, c = f & 15;
            uint32_t d = sbase + (uint32_t)r * FROW_B + c * 16;
            size_t so = (size_t)(b * SEQ + q0 + r) * DIM + hoff + c * 8;
            CPA16(d, (const void*)(Qhi_g + so));
            CPA16(d + 34816, (const void*)(Qlo_g + so));
        }
        CP_COMMIT();
        CP_WAIT(0);
        __syncthreads();
    }
    uint32_t qh[8][4], ql[8][4];
    {
        const uint32_t qrow = (uint32_t)(wq * 16 + (lane & 15));
        const uint32_t qc8  = (uint32_t)((lane >> 4) * 16);
#pragma unroll
        for (int ks = 0; ks < 8; ks++) {
            uint32_t ad = sbase + qrow * FROW_B + ks * 32 + qc8;
            LDM4(qh[ks], ad);
            LDM4(ql[ks], ad + 34816);
        }
    }
    __syncthreads();

#define FISSUE(kt) do { \
    const int k0 = (kt) * 32; \
    const uint32_t stb = sbase + ((kt) % FNSTAGE) * FSTAGE_B; \
    _Pragma("unroll") \
    for (int i = 0; i < 2; i++) { \
        int f = tid + i * 256; \
        int r = f >> 4, c = f & 15; \
        uint32_t d = stb + (uint32_t)r * FROW_B + c * 16; \
        size_t so = (size_t)(b * SEQ + k0 + r) * DIM + hoff + c * 8; \
        CPA16(d + FK_HI, (const void*)(Khi_g + so)); \
        CPA16(d + FK_LO, (const void*)(Klo_g + so)); \
        CPA16(d + FV_HI, (const void*)(Vhi_g + so)); \
        CPA16(d + FV_LO, (const void*)(Vlo_g + so)); \
    } \
    CP_COMMIT(); \
} while (0)

    float acc[16][4];
#pragma unroll
    for (int i = 0; i < 16; i++)
#pragma unroll
        for (int j = 0; j < 4; j++) acc[i][j] = 0.f;
    float m0 = -1e30f, m1 = -1e30f, l0 = 0.f, l1 = 0.f;

    const uint32_t krow = (uint32_t)(lane & 15);
    const uint32_t kc8  = (uint32_t)((lane >> 4) * 16);

    FISSUE(0); FISSUE(1);
    for (int kt = 0; kt < FITERS; kt++) {
        if (kt == FITERS - 1) { CP_WAIT(0); } else { CP_WAIT(1); }
        __syncthreads();
        if (kt + 2 < FITERS) FISSUE(kt + 2);
        const uint32_t stb = sbase + (kt % FNSTAGE) * FSTAGE_B;

        float s[4][4];
#pragma unroll
        for (int i = 0; i < 4; i++)
#pragma unroll
            for (int j = 0; j < 4; j++) s[i][j] = 0.f;
#pragma unroll
        for (int ks = 0; ks < 8; ks++) {
#pragma unroll
            for (int half = 0; half < 2; half++) {
                uint32_t kbh[4], kbl[4];
                uint32_t kd = stb + FK_HI + (half * 16 + krow) * FROW_B + ks * 32 + kc8;
                LDM4(kbh, kd);
                LDM4(kbl, kd + FK_LO);
                MMA_F16(s[2 * half + 0], qh[ks], kbh[0], kbh[2]);
                MMA_F16(s[2 * half + 0], qh[ks], kbl[0], kbl[2]);
                MMA_F16(s[2 * half + 0], ql[ks], kbh[0], kbh[2]);
                MMA_F16(s[2 * half + 1], qh[ks], kbh[1], kbh[3]);
                MMA_F16(s[2 * half + 1], qh[ks], kbl[1], kbl[3]);
                MMA_F16(s[2 * half + 1], ql[ks], kbh[1], kbh[3]);
            }
        }
#pragma unroll
        for (int i = 0; i < 4; i++)
#pragma unroll
            for (int j = 0; j < 4; j++) s[i][j] *= SCALEF;

        float mx0 = fmaxf(fmaxf(s[0][0], s[0][1]), fmaxf(s[1][0], s[1][1]));
        mx0 = fmaxf(mx0, fmaxf(fmaxf(s[2][0], s[2][1]), fmaxf(s[3][0], s[3][1])));
        float mx1 = fmaxf(fmaxf(s[0][2], s[0][3]), fmaxf(s[1][2], s[1][3]));
        mx1 = fmaxf(mx1, fmaxf(fmaxf(s[2][2], s[2][3]), fmaxf(s[3][2], s[3][3])));
#pragma unroll
        for (int o = 1; o <= 2; o <<= 1) {
            mx0 = fmaxf(mx0, __shfl_xor_sync(0xffffffffu, mx0, o));
            mx1 = fmaxf(mx1, __shfl_xor_sync(0xffffffffu, mx1, o));
        }
        float mn0 = fmaxf(m0, mx0), mn1 = fmaxf(m1, mx1);
        float f0 = __expf(m0 - mn0), f1 = __expf(m1 - mn1);
        m0 = mn0; m1 = mn1;
        float rs0 = 0.f, rs1 = 0.f;
#pragma unroll
        for (int nt = 0; nt < 4; nt++) {
            s[nt][0] = __expf(s[nt][0] - mn0);
            s[nt][1] = __expf(s[nt][1] - mn0);
            s[nt][2] = __expf(s[nt][2] - mn1);
            s[nt][3] = __expf(s[nt][3] - mn1);
            rs0 += s[nt][0] + s[nt][1];
            rs1 += s[nt][2] + s[nt][3];
        }
#pragma unroll
        for (int o = 1; o <= 2; o <<= 1) {
            rs0 += __shfl_xor_sync(0xffffffffu, rs0, o);
            rs1 += __shfl_xor_sync(0xffffffffu, rs1, o);
        }
        l0 = l0 * f0 + rs0;
        l1 = l1 * f1 + rs1;
#pragma unroll
        for (int i = 0; i < 16; i++) {
            acc[i][0] *= f0; acc[i][1] *= f0;
            acc[i][2] *= f1; acc[i][3] *= f1;
        }

        uint32_t ph[2][4];
#pragma unroll
        for (int k2 = 0; k2 < 2; k2++) {
            ph[k2][0] = pack_h2(s[2 * k2][0],     s[2 * k2][1]);
            ph[k2][1] = pack_h2(s[2 * k2][2],     s[2 * k2][3]);
            ph[k2][2] = pack_h2(s[2 * k2 + 1][0], s[2 * k2 + 1][1]);
            ph[k2][3] = pack_h2(s[2 * k2 + 1][2], s[2 * k2 + 1][3]);
        }
#pragma unroll
        for (int ng = 0; ng < 8; ng++) {
#pragma unroll
            for (int k2 = 0; k2 < 2; k2++) {
                uint32_t vbh[4], vbl[4];
                uint32_t vd = stb + FV_HI + (k2 * 16 + krow) * FROW_B + ng * 32 + kc8;
                LDM4T(vbh, vd);
                LDM4T(vbl, vd + (FV_LO - FV_HI));
                MMA_F16(acc[2 * ng + 0], ph[k2], vbh[0], vbh[1]);
                MMA_F16(acc[2 * ng + 0], ph[k2], vbl[0], vbl[1]);
                MMA_F16(acc[2 * ng + 1], ph[k2], vbh[2], vbh[3]);
                MMA_F16(acc[2 * ng + 1], ph[k2], vbl[2], vbl[3]);
            }
        }
    }

    float inv0 = 1.0f / l0, inv1 = 1.0f / l1;
    const int r0g = b * SEQ + q0 + wq * 16 + (lane >> 2);
#pragma unroll
    for (int nt = 0; nt < 16; nt++) {
        int cc = (int)hoff + nt * 8 + ((lane & 3) << 1);
        *(uint32_t*)(Ohi + (size_t)r0g * DIM + cc) =
            pack_h2(acc[nt][0] * inv0, acc[nt][1] * inv0);
        *(uint32_t*)(Ohi + (size_t)(r0g + 8) * DIM + cc) =
            pack_h2(acc[nt][2] * inv1, acc[nt][3] * inv1);
    }
#undef FISSUE
}

// ---------------------------------------------------------------------------
extern "C" void kernel_launch(void* const* d_in, const int* in_sizes, int n_in,
                              void* d_out, int out_size)
{
    (void)in_sizes; (void)n_in; (void)out_size;
    const float* x     = (const float*)d_in[0];
    const float* ctx   = (const float*)d_in[1];
    const float* cosb  = (const float*)d_in[2];
    const float* sinb  = (const float*)d_in[3];
    const float* bq    = (const float*)d_in[5];
    const float* bk    = (const float*)d_in[7];
    const float* bv    = (const float*)d_in[9];
    const float* bqc   = (const float*)d_in[11];
    const float* bkc   = (const float*)d_in[13];
    const float* bvc   = (const float*)d_in[15];
    const float* b_out = (const float*)d_in[17];
    const float* b_add = (const float*)d_in[19];
    const float* g_q   = (const float*)d_in[20];
    const float* g_k   = (const float*)d_in[21];
    const float* g_qc  = (const float*)d_in[22];
    const float* g_kc  = (const float*)d_in[23];
    float* out = (float*)d_out;

    __half *Whi, *Xhi, *Qhi, *Qlo, *Khi, *Klo, *Vhi, *Vlo;
    cudaGetSymbolAddress((void**)&Whi, g_Whi);
    cudaGetSymbolAddress((void**)&Xhi, g_Xhi);
    cudaGetSymbolAddress((void**)&Qhi, g_Qhi);
    cudaGetSymbolAddress((void**)&Qlo, g_Qlo);
    cudaGetSymbolAddress((void**)&Khi, g_Khi);
    cudaGetSymbolAddress((void**)&Klo, g_Klo);
    cudaGetSymbolAddress((void**)&Vhi, g_Vhi);
    cudaGetSymbolAddress((void**)&Vlo, g_Vlo);

    cudaFuncSetAttribute(mma_gemm_kernel,
                         cudaFuncAttributeMaxDynamicSharedMemorySize, GEMM_SMEM_BYTES);
    cudaFuncSetAttribute(flash_mma_kernel,
                         cudaFuncAttributeMaxDynamicSharedMemorySize, FLASH_SMEM_BYTES);

    const int WN4 = DIM * DIM / 4;

    // convert all 8 weights to fp16 hi (one launch)
    conv_w8_kernel<<<dim3((WN4 + 255) / 256, 8), 256>>>(
        (const float4*)d_in[4],  (const float4*)d_in[6],  (const float4*)d_in[8],
        (const float4*)d_in[10], (const float4*)d_in[12], (const float4*)d_in[14],
        (const float4*)d_in[16], (const float4*)d_in[18],
        (uint2*)Whi, WN4);

    // activations -> fp16 hi, joint layout
    conv_hi_kernel<<<(BB * S_TXT * (DIM / 4) + 255) / 256, 256>>>(
        (const float4*)ctx, (uint2*)Xhi, S_TXT, 0);
    conv_hi_kernel<<<(BB * S_IMG * (DIM / 4) + 255) / 256, 256>>>(
        (const float4*)x, (uint2*)Xhi, S_IMG, S_TXT);

    // QKV projections: ONE launch over all joint tiles (txt/img picked per tile)
    dim3 gQKV(DIM / 128, (BB * SEQ) / 128, 3);   // (24, 24, 3)
    mma_gemm_kernel<<<gQKV, 256, GEMM_SMEM_BYTES>>>(0, Xhi, Whi,
        bq, bk, bv, bqc, bkc, bvc, b_out, b_add,
        g_q, g_k, g_qc, g_kc, cosb, sinb,
        Qhi, Qlo, Khi, Klo, Vhi, Vlo, nullptr);

    // Flash attention (writes fp16 hi output into Xhi)
    flash_mma_kernel<<<dim3(SEQ / 128, BB * HEADS), 256, FLASH_SMEM_BYTES>>>(
        Qhi, Qlo, Khi, Klo, Vhi, Vlo, Xhi);

    // output projections: ONE launch (w_add/w_out picked per tile, rows remapped)
    dim3 gOut(DIM / 128, (BB * SEQ) / 128, 1);   // (24, 24, 1)
    mma_gemm_kernel<<<gOut, 256, GEMM_SMEM_BYTES>>>(1, Xhi, Whi,
        bq, bk, bv, bqc, bkc, bvc, b_out, b_add,
        g_q, g_k, g_qc, g_kc, cosb, sinb,
        Qhi, Qlo, Khi, Klo, Vhi, Vlo, out);
}

// round 12
// speedup vs baseline: 1.7701x; 1.0787x over previous
#include <cuda_runtime.h>
#include <cuda_fp16.h>
#include <cstdint>
#include <math.h>

#define BB 2
#define S_IMG 1024
#define S_TXT 512
#define SEQ 1536
#define DIM 3072
#define HEADS 24
#define HD 128
#define EPSF 1e-6f
#define SCALEF 0.08838834764831845f

// Scratch (device globals -- no allocation allowed)
__device__ __half g_Whi[8 * DIM * DIM];
__device__ __half g_Xhi[BB * SEQ * DIM];
__device__ __half g_Qhi[BB * SEQ * DIM];
__device__ __half g_Qlo[BB * SEQ * DIM];
__device__ __half g_Khi[BB * SEQ * DIM];
__device__ __half g_Klo[BB * SEQ * DIM];
__device__ __half g_Vhi[BB * SEQ * DIM];
__device__ __half g_Vlo[BB * SEQ * DIM];

// ===========================================================================
// helpers
// ===========================================================================
__device__ __forceinline__ uint32_t smem_u32(const void* p) {
    uint32_t a;
    asm("{ .reg .u64 t; cvta.to.shared.u64 t, %1; cvt.u32.u64 %0, t; }"
        : "=r"(a) : "l"(p));
    return a;
}
#define LDM4(r, a) \
    asm volatile("ldmatrix.sync.aligned.m8n8.x4.shared.b16 {%0,%1,%2,%3}, [%4];" \
        : "=r"((r)[0]), "=r"((r)[1]), "=r"((r)[2]), "=r"((r)[3]) : "r"(a))
#define LDM4T(r, a) \
    asm volatile("ldmatrix.sync.aligned.m8n8.x4.trans.shared.b16 {%0,%1,%2,%3}, [%4];" \
        : "=r"((r)[0]), "=r"((r)[1]), "=r"((r)[2]), "=r"((r)[3]) : "r"(a))
#define MMA_F16(d, a, b0, b1) \
    asm volatile("mma.sync.aligned.m16n8k16.row.col.f32.f16.f16.f32 " \
        "{%0,%1,%2,%3}, {%4,%5,%6,%7}, {%8,%9}, {%0,%1,%2,%3};" \
        : "+f"((d)[0]), "+f"((d)[1]), "+f"((d)[2]), "+f"((d)[3]) \
        : "r"((a)[0]), "r"((a)[1]), "r"((a)[2]), "r"((a)[3]), "r"(b0), "r"(b1))
#define CPA16(dst, src) \
    asm volatile("cp.async.cg.shared.global [%0], [%1], 16;" :: "r"(dst), "l"(src))
#define CP_COMMIT() asm volatile("cp.async.commit_group;" ::: "memory")
#define CP_WAIT(n)  asm volatile("cp.async.wait_group %0;" :: "n"(n) : "memory")

__device__ __forceinline__ uint32_t pack_h2(float a, float b) {
    __half2 h = __floats2half2_rn(a, b);
    return *(uint32_t*)&h;
}
__device__ __forceinline__ void split2(float a, float b, uint32_t& hi, uint32_t& lo) {
    __half ha = __float2half_rn(a), hb = __float2half_rn(b);
    __half la = __float2half_rn(a - __half2float(ha));
    __half lb = __float2half_rn(b - __half2float(hb));
    hi = ((uint32_t)__half_as_ushort(hb) << 16) | __half_as_ushort(ha);
    lo = ((uint32_t)__half_as_ushort(lb) << 16) | __half_as_ushort(la);
}

// ---------------------------------------------------------------------------
// conversion kernels
// ---------------------------------------------------------------------------
__global__ void __launch_bounds__(256) conv_w8_kernel(
    const float4* __restrict__ w0, const float4* __restrict__ w1,
    const float4* __restrict__ w2, const float4* __restrict__ w3,
    const float4* __restrict__ w4, const float4* __restrict__ w5,
    const float4* __restrict__ w6, const float4* __restrict__ w7,
    uint2* __restrict__ hi, int n4)
{
    int i = blockIdx.x * 256 + threadIdx.x;
    int z = blockIdx.y;
    if (i < n4) {
        const float4* src = (z == 0) ? w0 : (z == 1) ? w1 : (z == 2) ? w2 : (z == 3) ? w3
                          : (z == 4) ? w4 : (z == 5) ? w5 : (z == 6) ? w6 : w7;
        float4 v = src[i];
        uint2 ph;
        ph.x = pack_h2(v.x, v.y);
        ph.y = pack_h2(v.z, v.w);
        hi[(size_t)z * n4 + i] = ph;
    }
}

__global__ void __launch_bounds__(256) conv_hi_kernel(
    const float4* __restrict__ src, uint2* __restrict__ hi, int rpb, int dst_off)
{
    int i = blockIdx.x * 256 + threadIdx.x;
    int n4 = BB * rpb * (DIM / 4);
    if (i < n4) {
        int q = i % (DIM / 4);
        int row = i / (DIM / 4);
        int b = row / rpb, s = row % rpb;
        float4 v = src[i];
        uint2 ph;
        ph.x = pack_h2(v.x, v.y);
        ph.y = pack_h2(v.z, v.w);
        hi[(b * SEQ + dst_off + s) * (DIM / 4) + q] = ph;
    }
}

// ===========================================================================
// fp16 1-pass GEMM, tile 128x128, 128 threads = 4 warps each owning 64x64
// (2M x 2N). This halves the ldmatrix-per-MMA ratio vs 8x(64x32) warps.
// KC=32, 5-stage cp.async. Modes as in R11 (QKV fused epilogues / out-proj).
// ===========================================================================
#define KC 32
#define CHUNKS (DIM / KC)                  // 96
#define A_ST2 80
#define B_ST2 272
#define A_TILE_B (128 * A_ST2)              // 10240
#define B_TILE_B (32 * B_ST2)               // 8704
#define OFF_BHI A_TILE_B
#define STAGE_B (A_TILE_B + B_TILE_B)       // 18944
#define NSTAGE 5
#define GEMM_SMEM_BYTES (NSTAGE * STAGE_B)  // 94720

__global__ void __launch_bounds__(128, 2) mma_gemm_kernel(
    int mode,
    const __half* __restrict__ Xg,
    const __half* __restrict__ Whi_base,
    const float* bq, const float* bk, const float* bv,
    const float* bqc, const float* bkc, const float* bvc,
    const float* b_out, const float* b_add,
    const float* g_q, const float* g_k, const float* g_qc, const float* g_kc,
    const float* __restrict__ cosb, const float* __restrict__ sinb,
    __half* Qhi, __half* Qlo, __half* Khi, __half* Klo, __half* Vhi, __half* Vlo,
    float* out)
{
    extern __shared__ __align__(128) char smem[];
    const uint32_t sbase = smem_u32(smem);
    const int tid = threadIdx.x;
    const int wid = tid >> 5, lane = tid & 31;
    const int warp_m = wid >> 1;           // 2 groups of 64 rows
    const int warp_n = wid & 1;            // 2 groups of 64 cols
    const int z = blockIdx.z;

    const int row0 = blockIdx.y * 128;     // joint row (b*SEQ + sj)
    const int col0 = blockIdx.x * 128;
    const int b  = row0 / SEQ;
    const int sj = row0 % SEQ;
    const bool txt = (sj < S_TXT);

    int widx;
    const float* bias;
    __half *Hz = nullptr, *Lz = nullptr;
    const float* Gz = nullptr;
    float* C = nullptr;
    if (mode == 0) {
        widx = txt ? (3 + z) : z;
        bias = (z == 0) ? (txt ? bqc : bq) : (z == 1) ? (txt ? bkc : bk) : (txt ? bvc : bv);
        Hz = (z == 0) ? Qhi : (z == 1) ? Khi : Vhi;
        Lz = (z == 0) ? Qlo : (z == 1) ? Klo : Vlo;
        Gz = (z == 0) ? (txt ? g_qc : g_q) : (z == 1) ? (txt ? g_kc : g_k) : nullptr;
    } else {
        widx = txt ? 7 : 6;
        bias = txt ? b_add : b_out;
        size_t crow = txt ? (size_t)(b * S_TXT + sj)
                          : (size_t)(BB * S_TXT + b * S_IMG + (sj - S_TXT));
        C = out + crow * DIM;
    }
    const __half* Whi = Whi_base + (size_t)widx * DIM * DIM;
    const __half* Ahi = Xg + (size_t)row0 * DIM;

// 128 threads: 512 A-chunks + 512 B-chunks of 16B, 4+4 per thread
#define ISSUE(c) do { \
    const int k0 = (c) * KC; \
    const uint32_t stb = sbase + ((c) % NSTAGE) * STAGE_B; \
    _Pragma("unroll") \
    for (int i = 0; i < 4; i++) { \
        int f = tid + i * 128; \
        uint32_t d = stb + (uint32_t)(f >> 2) * A_ST2 + (f & 3) * 16; \
        size_t so = (size_t)(f >> 2) * DIM + k0 + ((f & 3) << 3); \
        CPA16(d, (const void*)(Ahi + so)); \
        uint32_t db = stb + OFF_BHI + (uint32_t)(f >> 4) * B_ST2 + (f & 15) * 16; \
        size_t sb2 = (size_t)(k0 + (f >> 4)) * DIM + col0 + ((f & 15) << 3); \
        CPA16(db, (const void*)(Whi + sb2)); \
    } \
    CP_COMMIT(); \
} while (0)

    float acc[4][8][4];
#pragma unroll
    for (int i = 0; i < 4; i++)
#pragma unroll
        for (int j = 0; j < 8; j++)
#pragma unroll
            for (int k = 0; k < 4; k++) acc[i][j][k] = 0.f;

    const uint32_t a_row = (uint32_t)(warp_m * 64 + (lane & 15));
    const uint32_t a_sel = (uint32_t)((lane >> 4) * 16);
    const uint32_t b_row = (uint32_t)(lane & 15);
    const uint32_t b_sel = (uint32_t)(warp_n * 128 + ((lane >> 4) * 16));  // bytes

#define COMPUTE(sidx) do { \
    const uint32_t sb = sbase + (sidx) * STAGE_B; \
    _Pragma("unroll") \
    for (int ks = 0; ks < 2; ks++) { \
        uint32_t ah[4][4]; \
        _Pragma("unroll") \
        for (int mt = 0; mt < 4; mt++) { \
            uint32_t ad = sb + (a_row + mt * 16) * A_ST2 + ks * 32 + a_sel; \
            LDM4(ah[mt], ad); \
        } \
        _Pragma("unroll") \
        for (int ng = 0; ng < 4; ng++) { \
            uint32_t bh[4]; \
            uint32_t bd = sb + OFF_BHI + (ks * 16 + b_row) * B_ST2 + b_sel + ng * 32; \
            LDM4T(bh, bd); \
            _Pragma("unroll") \
            for (int mt = 0; mt < 4; mt++) { \
                MMA_F16(acc[mt][ng * 2 + 0], ah[mt], bh[0], bh[1]); \
                MMA_F16(acc[mt][ng * 2 + 1], ah[mt], bh[2], bh[3]); \
            } \
        } \
    } \
} while (0)

    ISSUE(0); ISSUE(1); ISSUE(2); ISSUE(3);
    for (int c = 0; c < CHUNKS; c++) {
        if (c < CHUNKS - 3)      { CP_WAIT(3); }
        else if (c == CHUNKS - 3){ CP_WAIT(2); }
        else if (c == CHUNKS - 2){ CP_WAIT(1); }
        else                     { CP_WAIT(0); }
        __syncthreads();
        if (c + 4 < CHUNKS) ISSUE(c + 4);
        COMPUTE(c % NSTAGE);
    }

    // ---------------- epilogue ----------------
    const int m_base = warp_m * 64;
    const int n_loc  = warp_n * 64;

    // add bias
#pragma unroll
    for (int mt = 0; mt < 4; mt++)
#pragma unroll
        for (int nt = 0; nt < 8; nt++) {
            int cc = col0 + n_loc + nt * 8 + ((lane & 3) << 1);
            float b0 = bias[cc], b1 = bias[cc + 1];
            acc[mt][nt][0] += b0; acc[mt][nt][1] += b1;
            acc[mt][nt][2] += b0; acc[mt][nt][3] += b1;
        }

    if (mode == 1) {
#pragma unroll
        for (int mt = 0; mt < 4; mt++)
#pragma unroll
            for (int nt = 0; nt < 8; nt++) {
                int r  = m_base + mt * 16 + (lane >> 2);
                int cc = col0 + n_loc + nt * 8 + ((lane & 3) << 1);
                *(float2*)(C + (size_t)r * DIM + cc) =
                    make_float2(acc[mt][nt][0], acc[mt][nt][1]);
                *(float2*)(C + (size_t)(r + 8) * DIM + cc) =
                    make_float2(acc[mt][nt][2], acc[mt][nt][3]);
            }
    } else if (Gz == nullptr) {
        // V path: hi/lo split at joint rows
#pragma unroll
        for (int mt = 0; mt < 4; mt++)
#pragma unroll
            for (int nt = 0; nt < 8; nt++) {
                int r  = m_base + mt * 16 + (lane >> 2);
                int cc = col0 + n_loc + nt * 8 + ((lane & 3) << 1);
                uint32_t h0, l0, h1, l1;
                split2(acc[mt][nt][0], acc[mt][nt][1], h0, l0);
                split2(acc[mt][nt][2], acc[mt][nt][3], h1, l1);
                *(uint32_t*)(Hz + (size_t)(row0 + r) * DIM + cc) = h0;
                *(uint32_t*)(Lz + (size_t)(row0 + r) * DIM + cc) = l0;
                *(uint32_t*)(Hz + (size_t)(row0 + r + 8) * DIM + cc) = h1;
                *(uint32_t*)(Lz + (size_t)(row0 + r + 8) * DIM + cc) = l1;
            }
    } else {
        // Q/K path: RMS-norm over the 128-col head + RoPE + split
        __syncthreads();
        float* red = (float*)smem;           // [128][2]
        float ss[4][2];
#pragma unroll
        for (int mt = 0; mt < 4; mt++) {
            float p0 = 0.f, p1 = 0.f;
#pragma unroll
            for (int nt = 0; nt < 8; nt++) {
                p0 += acc[mt][nt][0] * acc[mt][nt][0] + acc[mt][nt][1] * acc[mt][nt][1];
                p1 += acc[mt][nt][2] * acc[mt][nt][2] + acc[mt][nt][3] * acc[mt][nt][3];
            }
            p0 += __shfl_xor_sync(0xffffffffu, p0, 1);
            p0 += __shfl_xor_sync(0xffffffffu, p0, 2);
            p1 += __shfl_xor_sync(0xffffffffu, p1, 1);
            p1 += __shfl_xor_sync(0xffffffffu, p1, 2);
            ss[mt][0] = p0; ss[mt][1] = p1;
        }
        if ((lane & 3) == 0) {
#pragma unroll
            for (int mt = 0; mt < 4; mt++) {
                int rl = m_base + mt * 16 + (lane >> 2);
                red[rl * 2 + warp_n] = ss[mt][0];
                red[(rl + 8) * 2 + warp_n] = ss[mt][1];
            }
        }
        __syncthreads();
#pragma unroll
        for (int mt = 0; mt < 4; mt++) {
            int rl = m_base + mt * 16 + (lane >> 2);
            float sm0 = red[rl * 2 + 0] + red[rl * 2 + 1];
            float sm1 = red[(rl + 8) * 2 + 0] + red[(rl + 8) * 2 + 1];
            float scl0 = rsqrtf(sm0 * (1.0f / HD) + EPSF);
            float scl1 = rsqrtf(sm1 * (1.0f / HD) + EPSF);
            int sp0 = sj + rl;
            int sp1 = sp0 + 8;
#pragma unroll
            for (int nt = 0; nt < 8; nt++) {
                int d  = n_loc + nt * 8 + ((lane & 3) << 1);
                int cc = col0 + d;
                float gd0 = Gz[d], gd1 = Gz[d + 1];
                float c0 = cosb[sp0 * (HD / 2) + (d >> 1)];
                float n0 = sinb[sp0 * (HD / 2) + (d >> 1)];
                float c1 = cosb[sp1 * (HD / 2) + (d >> 1)];
                float n1 = sinb[sp1 * (HD / 2) + (d >> 1)];
                float x0 = acc[mt][nt][0] * scl0 * gd0;
                float x1 = acc[mt][nt][1] * scl0 * gd1;
                float y0 = acc[mt][nt][2] * scl1 * gd0;
                float y1 = acc[mt][nt][3] * scl1 * gd1;
                uint32_t h0, l0, h1, l1;
                split2(x0 * c0 - x1 * n0, x0 * n0 + x1 * c0, h0, l0);
                split2(y0 * c1 - y1 * n1, y0 * n1 + y1 * c1, h1, l1);
                *(uint32_t*)(Hz + (size_t)(row0 + rl) * DIM + cc) = h0;
                *(uint32_t*)(Lz + (size_t)(row0 + rl) * DIM + cc) = l0;
                *(uint32_t*)(Hz + (size_t)(row0 + rl + 8) * DIM + cc) = h1;
                *(uint32_t*)(Lz + (size_t)(row0 + rl + 8) * DIM + cc) = l1;
            }
        }
    }
#undef ISSUE
#undef COMPUTE
}

// ===========================================================================
// Flash attention via mma.sync fp16 (R7/R10/R11-proven, unchanged).
// QK^T 3-pass (hi/lo), PV 2-pass (P hi). Output hi-only to Xhi.
// ===========================================================================
#define FROW_B 272
#define FK_HI 0
#define FK_LO (32 * FROW_B)
#define FV_HI (2 * 32 * FROW_B)
#define FV_LO (3 * 32 * FROW_B)
#define FSTAGE_B (4 * 32 * FROW_B)
#define FNSTAGE 3
#define FLASH_SMEM_BYTES (FNSTAGE * FSTAGE_B)
#define FITERS (SEQ / 32)

__global__ void __launch_bounds__(256) flash_mma_kernel(
    const __half* __restrict__ Qhi_g, const __half* __restrict__ Qlo_g,
    const __half* __restrict__ Khi_g, const __half* __restrict__ Klo_g,
    const __half* __restrict__ Vhi_g, const __half* __restrict__ Vlo_g,
    __half* __restrict__ Ohi)
{
    extern __shared__ __align__(128) char smem[];
    const uint32_t sbase = smem_u32(smem);
    const int tid = threadIdx.x;
    const int wq = tid >> 5, lane = tid & 31;
    const int q0 = blockIdx.x * 128;
    const int bh = blockIdx.y;
    const int b = bh / HEADS, h = bh % HEADS;
    const size_t hoff = (size_t)h * HD;

    {
#pragma unroll
        for (int i = 0; i < 8; i++) {
            int f = tid + i * 256;
            int r = f >> 4, c = f & 15;
            uint32_t d = sbase + (uint32_t)r * FROW_B + c * 16;
            size_t so = (size_t)(b * SEQ + q0 + r) * DIM + hoff + c * 8;
            CPA16(d, (const void*)(Qhi_g + so));
            CPA16(d + 34816, (const void*)(Qlo_g + so));
        }
        CP_COMMIT();
        CP_WAIT(0);
        __syncthreads();
    }
    uint32_t qh[8][4], ql[8][4];
    {
        const uint32_t qrow = (uint32_t)(wq * 16 + (lane & 15));
        const uint32_t qc8  = (uint32_t)((lane >> 4) * 16);
#pragma unroll
        for (int ks = 0; ks < 8; ks++) {
            uint32_t ad = sbase + qrow * FROW_B + ks * 32 + qc8;
            LDM4(qh[ks], ad);
            LDM4(ql[ks], ad + 34816);
        }
    }
    __syncthreads();

#define FISSUE(kt) do { \
    const int k0 = (kt) * 32; \
    const uint32_t stb = sbase + ((kt) % FNSTAGE) * FSTAGE_B; \
    _Pragma("unroll") \
    for (int i = 0; i < 2; i++) { \
        int f = tid + i * 256; \
        int r = f >> 4, c = f & 15; \
        uint32_t d = stb + (uint32_t)r * FROW_B + c * 16; \
        size_t so = (size_t)(b * SEQ + k0 + r) * DIM + hoff + c * 8; \
        CPA16(d + FK_HI, (const void*)(Khi_g + so)); \
        CPA16(d + FK_LO, (const void*)(Klo_g + so)); \
        CPA16(d + FV_HI, (const void*)(Vhi_g + so)); \
        CPA16(d + FV_LO, (const void*)(Vlo_g + so)); \
    } \
    CP_COMMIT(); \
} while (0)

    float acc[16][4];
#pragma unroll
    for (int i = 0; i < 16; i++)
#pragma unroll
        for (int j = 0; j < 4; j++) acc[i][j] = 0.f;
    float m0 = -1e30f, m1 = -1e30f, l0 = 0.f, l1 = 0.f;

    const uint32_t krow = (uint32_t)(lane & 15);
    const uint32_t kc8  = (uint32_t)((lane >> 4) * 16);

    FISSUE(0); FISSUE(1);
    for (int kt = 0; kt < FITERS; kt++) {
        if (kt == FITERS - 1) { CP_WAIT(0); } else { CP_WAIT(1); }
        __syncthreads();
        if (kt + 2 < FITERS) FISSUE(kt + 2);
        const uint32_t stb = sbase + (kt % FNSTAGE) * FSTAGE_B;

        float s[4][4];
#pragma unroll
        for (int i = 0; i < 4; i++)
#pragma unroll
            for (int j = 0; j < 4; j++) s[i][j] = 0.f;
#pragma unroll
        for (int ks = 0; ks < 8; ks++) {
#pragma unroll
            for (int half = 0; half < 2; half++) {
                uint32_t kbh[4], kbl[4];
                uint32_t kd = stb + FK_HI + (half * 16 + krow) * FROW_B + ks * 32 + kc8;
                LDM4(kbh, kd);
                LDM4(kbl, kd + FK_LO);
                MMA_F16(s[2 * half + 0], qh[ks], kbh[0], kbh[2]);
                MMA_F16(s[2 * half + 0], qh[ks], kbl[0], kbl[2]);
                MMA_F16(s[2 * half + 0], ql[ks], kbh[0], kbh[2]);
                MMA_F16(s[2 * half + 1], qh[ks], kbh[1], kbh[3]);
                MMA_F16(s[2 * half + 1], qh[ks], kbl[1], kbl[3]);
                MMA_F16(s[2 * half + 1], ql[ks], kbh[1], kbh[3]);
            }
        }
#pragma unroll
        for (int i = 0; i < 4; i++)
#pragma unroll
            for (int j = 0; j < 4; j++) s[i][j] *= SCALEF;

        float mx0 = fmaxf(fmaxf(s[0][0], s[0][1]), fmaxf(s[1][0], s[1][1]));
        mx0 = fmaxf(mx0, fmaxf(fmaxf(s[2][0], s[2][1]), fmaxf(s[3][0], s[3][1])));
        float mx1 = fmaxf(fmaxf(s[0][2], s[0][3]), fmaxf(s[1][2], s[1][3]));
        mx1 = fmaxf(mx1, fmaxf(fmaxf(s[2][2], s[2][3]), fmaxf(s[3][2], s[3][3])));
#pragma unroll
        for (int o = 1; o <= 2; o <<= 1) {
            mx0 = fmaxf(mx0, __shfl_xor_sync(0xffffffffu, mx0, o));
            mx1 = fmaxf(mx1, __shfl_xor_sync(0xffffffffu, mx1, o));
        }
        float mn0 = fmaxf(m0, mx0), mn1 = fmaxf(m1, mx1);
        float f0 = __expf(m0 - mn0), f1 = __expf(m1 - mn1);
        m0 = mn0; m1 = mn1;
        float rs0 = 0.f, rs1 = 0.f;
#pragma unroll
        for (int nt = 0; nt < 4; nt++) {
            s[nt][0] = __expf(s[nt][0] - mn0);
            s[nt][1] = __expf(s[nt][1] - mn0);
            s[nt][2] = __expf(s[nt][2] - mn1);
            s[nt][3] = __expf(s[nt][3] - mn1);
            rs0 += s[nt][0] + s[nt][1];
            rs1 += s[nt][2] + s[nt][3];
        }
#pragma unroll
        for (int o = 1; o <= 2; o <<= 1) {
            rs0 += __shfl_xor_sync(0xffffffffu, rs0, o);
            rs1 += __shfl_xor_sync(0xffffffffu, rs1, o);
        }
        l0 = l0 * f0 + rs0;
        l1 = l1 * f1 + rs1;
#pragma unroll
        for (int i = 0; i < 16; i++) {
            acc[i][0] *= f0; acc[i][1] *= f0;
            acc[i][2] *= f1; acc[i][3] *= f1;
        }

        uint32_t ph[2][4];
#pragma unroll
        for (int k2 = 0; k2 < 2; k2++) {
            ph[k2][0] = pack_h2(s[2 * k2][0],     s[2 * k2][1]);
            ph[k2][1] = pack_h2(s[2 * k2][2],     s[2 * k2][3]);
            ph[k2][2] = pack_h2(s[2 * k2 + 1][0], s[2 * k2 + 1][1]);
            ph[k2][3] = pack_h2(s[2 * k2 + 1][2], s[2 * k2 + 1][3]);
        }
#pragma unroll
        for (int ng = 0; ng < 8; ng++) {
#pragma unroll
            for (int k2 = 0; k2 < 2; k2++) {
                uint32_t vbh[4], vbl[4];
                uint32_t vd = stb + FV_HI + (k2 * 16 + krow) * FROW_B + ng * 32 + kc8;
                LDM4T(vbh, vd);
                LDM4T(vbl, vd + (FV_LO - FV_HI));
                MMA_F16(acc[2 * ng + 0], ph[k2], vbh[0], vbh[1]);
                MMA_F16(acc[2 * ng + 0], ph[k2], vbl[0], vbl[1]);
                MMA_F16(acc[2 * ng + 1], ph[k2], vbh[2], vbh[3]);
                MMA_F16(acc[2 * ng + 1], ph[k2], vbl[2], vbl[3]);
            }
        }
    }

    float inv0 = 1.0f / l0, inv1 = 1.0f / l1;
    const int r0g = b * SEQ + q0 + wq * 16 + (lane >> 2);
#pragma unroll
    for (int nt = 0; nt < 16; nt++) {
        int cc = (int)hoff + nt * 8 + ((lane & 3) << 1);
        *(uint32_t*)(Ohi + (size_t)r0g * DIM + cc) =
            pack_h2(acc[nt][0] * inv0, acc[nt][1] * inv0);
        *(uint32_t*)(Ohi + (size_t)(r0g + 8) * DIM + cc) =
            pack_h2(acc[nt][2] * inv1, acc[nt][3] * inv1);
    }
#undef FISSUE
}

// ---------------------------------------------------------------------------
extern "C" void kernel_launch(void* const* d_in, const int* in_sizes, int n_in,
                              void* d_out, int out_size)
{
    (void)in_sizes; (void)n_in; (void)out_size;
    const float* x     = (const float*)d_in[0];
    const float* ctx   = (const float*)d_in[1];
    const float* cosb  = (const float*)d_in[2];
    const float* sinb  = (const float*)d_in[3];
    const float* bq    = (const float*)d_in[5];
    const float* bk    = (const float*)d_in[7];
    const float* bv    = (const float*)d_in[9];
    const float* bqc   = (const float*)d_in[11];
    const float* bkc   = (const float*)d_in[13];
    const float* bvc   = (const float*)d_in[15];
    const float* b_out = (const float*)d_in[17];
    const float* b_add = (const float*)d_in[19];
    const float* g_q   = (const float*)d_in[20];
    const float* g_k   = (const float*)d_in[21];
    const float* g_qc  = (const float*)d_in[22];
    const float* g_kc  = (const float*)d_in[23];
    float* out = (float*)d_out;

    __half *Whi, *Xhi, *Qhi, *Qlo, *Khi, *Klo, *Vhi, *Vlo;
    cudaGetSymbolAddress((void**)&Whi, g_Whi);
    cudaGetSymbolAddress((void**)&Xhi, g_Xhi);
    cudaGetSymbolAddress((void**)&Qhi, g_Qhi);
    cudaGetSymbolAddress((void**)&Qlo, g_Qlo);
    cudaGetSymbolAddress((void**)&Khi, g_Khi);
    cudaGetSymbolAddress((void**)&Klo, g_Klo);
    cudaGetSymbolAddress((void**)&Vhi, g_Vhi);
    cudaGetSymbolAddress((void**)&Vlo, g_Vlo);

    cudaFuncSetAttribute(mma_gemm_kernel,
                         cudaFuncAttributeMaxDynamicSharedMemorySize, GEMM_SMEM_BYTES);
    cudaFuncSetAttribute(flash_mma_kernel,
                         cudaFuncAttributeMaxDynamicSharedMemorySize, FLASH_SMEM_BYTES);

    const int WN4 = DIM * DIM / 4;

    // convert all 8 weights to fp16 hi (one launch)
    conv_w8_kernel<<<dim3((WN4 + 255) / 256, 8), 256>>>(
        (const float4*)d_in[4],  (const float4*)d_in[6],  (const float4*)d_in[8],
        (const float4*)d_in[10], (const float4*)d_in[12], (const float4*)d_in[14],
        (const float4*)d_in[16], (const float4*)d_in[18],
        (uint2*)Whi, WN4);

    // activations -> fp16 hi, joint layout
    conv_hi_kernel<<<(BB * S_TXT * (DIM / 4) + 255) / 256, 256>>>(
        (const float4*)ctx, (uint2*)Xhi, S_TXT, 0);
    conv_hi_kernel<<<(BB * S_IMG * (DIM / 4) + 255) / 256, 256>>>(
        (const float4*)x, (uint2*)Xhi, S_IMG, S_TXT);

    // QKV projections: ONE launch, 128-thread CTAs
    dim3 gQKV(DIM / 128, (BB * SEQ) / 128, 3);   // (24, 24, 3)
    mma_gemm_kernel<<<gQKV, 128, GEMM_SMEM_BYTES>>>(0, Xhi, Whi,
        bq, bk, bv, bqc, bkc, bvc, b_out, b_add,
        g_q, g_k, g_qc, g_kc, cosb, sinb,
        Qhi, Qlo, Khi, Klo, Vhi, Vlo, nullptr);

    // Flash attention (writes fp16 hi output into Xhi)
    flash_mma_kernel<<<dim3(SEQ / 128, BB * HEADS), 256, FLASH_SMEM_BYTES>>>(
        Qhi, Qlo, Khi, Klo, Vhi, Vlo, Xhi);

    // output projections: ONE launch
    dim3 gOut(DIM / 128, (BB * SEQ) / 128, 1);   // (24, 24, 1)
    mma_gemm_kernel<<<gOut, 128, GEMM_SMEM_BYTES>>>(1, Xhi, Whi,
        bq, bk, bv, bqc, bkc, bvc, b_out, b_add,
        g_q, g_k, g_qc, g_kc, cosb, sinb,
        Qhi, Qlo, Khi, Klo, Vhi, Vlo, out);
}

// round 13
// speedup vs baseline: 1.9273x; 1.0888x over previous
#include <cuda_runtime.h>
#include <cuda_fp16.h>
#include <cstdint>
#include <math.h>

#define BB 2
#define S_IMG 1024
#define S_TXT 512
#define SEQ 1536
#define DIM 3072
#define HEADS 24
#define HD 128
#define EPSF 1e-6f
#define SCALEF 0.08838834764831845f

// Scratch (device globals -- no allocation allowed)
__device__ __half g_Whi[8 * DIM * DIM];
__device__ __half g_Xhi[BB * SEQ * DIM];
__device__ __half g_Qhi[BB * SEQ * DIM];
__device__ __half g_Qlo[BB * SEQ * DIM];
__device__ __half g_Khi[BB * SEQ * DIM];
__device__ __half g_Klo[BB * SEQ * DIM];
__device__ __half g_Vhi[BB * SEQ * DIM];
__device__ __half g_Vlo[BB * SEQ * DIM];

// ===========================================================================
// helpers
// ===========================================================================
__device__ __forceinline__ uint32_t smem_u32(const void* p) {
    uint32_t a;
    asm("{ .reg .u64 t; cvta.to.shared.u64 t, %1; cvt.u32.u64 %0, t; }"
        : "=r"(a) : "l"(p));
    return a;
}
#define LDM4(r, a) \
    asm volatile("ldmatrix.sync.aligned.m8n8.x4.shared.b16 {%0,%1,%2,%3}, [%4];" \
        : "=r"((r)[0]), "=r"((r)[1]), "=r"((r)[2]), "=r"((r)[3]) : "r"(a))
#define LDM4T(r, a) \
    asm volatile("ldmatrix.sync.aligned.m8n8.x4.trans.shared.b16 {%0,%1,%2,%3}, [%4];" \
        : "=r"((r)[0]), "=r"((r)[1]), "=r"((r)[2]), "=r"((r)[3]) : "r"(a))
#define MMA_F16(d, a, b0, b1) \
    asm volatile("mma.sync.aligned.m16n8k16.row.col.f32.f16.f16.f32 " \
        "{%0,%1,%2,%3}, {%4,%5,%6,%7}, {%8,%9}, {%0,%1,%2,%3};" \
        : "+f"((d)[0]), "+f"((d)[1]), "+f"((d)[2]), "+f"((d)[3]) \
        : "r"((a)[0]), "r"((a)[1]), "r"((a)[2]), "r"((a)[3]), "r"(b0), "r"(b1))
#define CPA16(dst, src) \
    asm volatile("cp.async.cg.shared.global [%0], [%1], 16;" :: "r"(dst), "l"(src))
#define CP_COMMIT() asm volatile("cp.async.commit_group;" ::: "memory")
#define CP_WAIT(n)  asm volatile("cp.async.wait_group %0;" :: "n"(n) : "memory")

__device__ __forceinline__ uint32_t pack_h2(float a, float b) {
    __half2 h = __floats2half2_rn(a, b);
    return *(uint32_t*)&h;
}
__device__ __forceinline__ void split2(float a, float b, uint32_t& hi, uint32_t& lo) {
    __half ha = __float2half_rn(a), hb = __float2half_rn(b);
    __half la = __float2half_rn(a - __half2float(ha));
    __half lb = __float2half_rn(b - __half2float(hb));
    hi = ((uint32_t)__half_as_ushort(hb) << 16) | __half_as_ushort(ha);
    lo = ((uint32_t)__half_as_ushort(lb) << 16) | __half_as_ushort(la);
}

// ---------------------------------------------------------------------------
// conversion kernels
// ---------------------------------------------------------------------------
__global__ void __launch_bounds__(256) conv_w8_kernel(
    const float4* __restrict__ w0, const float4* __restrict__ w1,
    const float4* __restrict__ w2, const float4* __restrict__ w3,
    const float4* __restrict__ w4, const float4* __restrict__ w5,
    const float4* __restrict__ w6, const float4* __restrict__ w7,
    uint2* __restrict__ hi, int n4)
{
    int i = blockIdx.x * 256 + threadIdx.x;
    int z = blockIdx.y;
    if (i < n4) {
        const float4* src = (z == 0) ? w0 : (z == 1) ? w1 : (z == 2) ? w2 : (z == 3) ? w3
                          : (z == 4) ? w4 : (z == 5) ? w5 : (z == 6) ? w6 : w7;
        float4 v = src[i];
        uint2 ph;
        ph.x = pack_h2(v.x, v.y);
        ph.y = pack_h2(v.z, v.w);
        hi[(size_t)z * n4 + i] = ph;
    }
}

__global__ void __launch_bounds__(256) conv_hi_kernel(
    const float4* __restrict__ src, uint2* __restrict__ hi, int rpb, int dst_off)
{
    int i = blockIdx.x * 256 + threadIdx.x;
    int n4 = BB * rpb * (DIM / 4);
    if (i < n4) {
        int q = i % (DIM / 4);
        int row = i / (DIM / 4);
        int b = row / rpb, s = row % rpb;
        float4 v = src[i];
        uint2 ph;
        ph.x = pack_h2(v.x, v.y);
        ph.y = pack_h2(v.z, v.w);
        hi[(b * SEQ + dst_off + s) * (DIM / 4) + q] = ph;
    }
}

// ===========================================================================
// fp16 1-pass GEMM, tile 128x128, 128 threads = 4 warps each owning 64x64
// (R12-proven). KC=32, 5-stage cp.async. Fused epilogues as in R11/R12.
// ===========================================================================
#define KC 32
#define CHUNKS (DIM / KC)                  // 96
#define A_ST2 80
#define B_ST2 272
#define A_TILE_B (128 * A_ST2)              // 10240
#define B_TILE_B (32 * B_ST2)               // 8704
#define OFF_BHI A_TILE_B
#define STAGE_B (A_TILE_B + B_TILE_B)       // 18944
#define NSTAGE 5
#define GEMM_SMEM_BYTES (NSTAGE * STAGE_B)  // 94720

__global__ void __launch_bounds__(128, 2) mma_gemm_kernel(
    int mode,
    const __half* __restrict__ Xg,
    const __half* __restrict__ Whi_base,
    const float* bq, const float* bk, const float* bv,
    const float* bqc, const float* bkc, const float* bvc,
    const float* b_out, const float* b_add,
    const float* g_q, const float* g_k, const float* g_qc, const float* g_kc,
    const float* __restrict__ cosb, const float* __restrict__ sinb,
    __half* Qhi, __half* Qlo, __half* Khi, __half* Klo, __half* Vhi, __half* Vlo,
    float* out)
{
    extern __shared__ __align__(128) char smem[];
    const uint32_t sbase = smem_u32(smem);
    const int tid = threadIdx.x;
    const int wid = tid >> 5, lane = tid & 31;
    const int warp_m = wid >> 1;
    const int warp_n = wid & 1;
    const int z = blockIdx.z;

    const int row0 = blockIdx.y * 128;
    const int col0 = blockIdx.x * 128;
    const int b  = row0 / SEQ;
    const int sj = row0 % SEQ;
    const bool txt = (sj < S_TXT);

    int widx;
    const float* bias;
    __half *Hz = nullptr, *Lz = nullptr;
    const float* Gz = nullptr;
    float* C = nullptr;
    if (mode == 0) {
        widx = txt ? (3 + z) : z;
        bias = (z == 0) ? (txt ? bqc : bq) : (z == 1) ? (txt ? bkc : bk) : (txt ? bvc : bv);
        Hz = (z == 0) ? Qhi : (z == 1) ? Khi : Vhi;
        Lz = (z == 0) ? Qlo : (z == 1) ? Klo : Vlo;
        Gz = (z == 0) ? (txt ? g_qc : g_q) : (z == 1) ? (txt ? g_kc : g_k) : nullptr;
    } else {
        widx = txt ? 7 : 6;
        bias = txt ? b_add : b_out;
        size_t crow = txt ? (size_t)(b * S_TXT + sj)
                          : (size_t)(BB * S_TXT + b * S_IMG + (sj - S_TXT));
        C = out + crow * DIM;
    }
    const __half* Whi = Whi_base + (size_t)widx * DIM * DIM;
    const __half* Ahi = Xg + (size_t)row0 * DIM;

#define ISSUE(c) do { \
    const int k0 = (c) * KC; \
    const uint32_t stb = sbase + ((c) % NSTAGE) * STAGE_B; \
    _Pragma("unroll") \
    for (int i = 0; i < 4; i++) { \
        int f = tid + i * 128; \
        uint32_t d = stb + (uint32_t)(f >> 2) * A_ST2 + (f & 3) * 16; \
        size_t so = (size_t)(f >> 2) * DIM + k0 + ((f & 3) << 3); \
        CPA16(d, (const void*)(Ahi + so)); \
        uint32_t db = stb + OFF_BHI + (uint32_t)(f >> 4) * B_ST2 + (f & 15) * 16; \
        size_t sb2 = (size_t)(k0 + (f >> 4)) * DIM + col0 + ((f & 15) << 3); \
        CPA16(db, (const void*)(Whi + sb2)); \
    } \
    CP_COMMIT(); \
} while (0)

    float acc[4][8][4];
#pragma unroll
    for (int i = 0; i < 4; i++)
#pragma unroll
        for (int j = 0; j < 8; j++)
#pragma unroll
            for (int k = 0; k < 4; k++) acc[i][j][k] = 0.f;

    const uint32_t a_row = (uint32_t)(warp_m * 64 + (lane & 15));
    const uint32_t a_sel = (uint32_t)((lane >> 4) * 16);
    const uint32_t b_row = (uint32_t)(lane & 15);
    const uint32_t b_sel = (uint32_t)(warp_n * 128 + ((lane >> 4) * 16));

#define COMPUTE(sidx) do { \
    const uint32_t sb = sbase + (sidx) * STAGE_B; \
    _Pragma("unroll") \
    for (int ks = 0; ks < 2; ks++) { \
        uint32_t ah[4][4]; \
        _Pragma("unroll") \
        for (int mt = 0; mt < 4; mt++) { \
            uint32_t ad = sb + (a_row + mt * 16) * A_ST2 + ks * 32 + a_sel; \
            LDM4(ah[mt], ad); \
        } \
        _Pragma("unroll") \
        for (int ng = 0; ng < 4; ng++) { \
            uint32_t bh[4]; \
            uint32_t bd = sb + OFF_BHI + (ks * 16 + b_row) * B_ST2 + b_sel + ng * 32; \
            LDM4T(bh, bd); \
            _Pragma("unroll") \
            for (int mt = 0; mt < 4; mt++) { \
                MMA_F16(acc[mt][ng * 2 + 0], ah[mt], bh[0], bh[1]); \
                MMA_F16(acc[mt][ng * 2 + 1], ah[mt], bh[2], bh[3]); \
            } \
        } \
    } \
} while (0)

    ISSUE(0); ISSUE(1); ISSUE(2); ISSUE(3);
    for (int c = 0; c < CHUNKS; c++) {
        if (c < CHUNKS - 3)      { CP_WAIT(3); }
        else if (c == CHUNKS - 3){ CP_WAIT(2); }
        else if (c == CHUNKS - 2){ CP_WAIT(1); }
        else                     { CP_WAIT(0); }
        __syncthreads();
        if (c + 4 < CHUNKS) ISSUE(c + 4);
        COMPUTE(c % NSTAGE);
    }

    // ---------------- epilogue ----------------
    const int m_base = warp_m * 64;
    const int n_loc  = warp_n * 64;

#pragma unroll
    for (int mt = 0; mt < 4; mt++)
#pragma unroll
        for (int nt = 0; nt < 8; nt++) {
            int cc = col0 + n_loc + nt * 8 + ((lane & 3) << 1);
            float b0 = bias[cc], b1 = bias[cc + 1];
            acc[mt][nt][0] += b0; acc[mt][nt][1] += b1;
            acc[mt][nt][2] += b0; acc[mt][nt][3] += b1;
        }

    if (mode == 1) {
#pragma unroll
        for (int mt = 0; mt < 4; mt++)
#pragma unroll
            for (int nt = 0; nt < 8; nt++) {
                int r  = m_base + mt * 16 + (lane >> 2);
                int cc = col0 + n_loc + nt * 8 + ((lane & 3) << 1);
                *(float2*)(C + (size_t)r * DIM + cc) =
                    make_float2(acc[mt][nt][0], acc[mt][nt][1]);
                *(float2*)(C + (size_t)(r + 8) * DIM + cc) =
                    make_float2(acc[mt][nt][2], acc[mt][nt][3]);
            }
    } else if (Gz == nullptr) {
#pragma unroll
        for (int mt = 0; mt < 4; mt++)
#pragma unroll
            for (int nt = 0; nt < 8; nt++) {
                int r  = m_base + mt * 16 + (lane >> 2);
                int cc = col0 + n_loc + nt * 8 + ((lane & 3) << 1);
                uint32_t h0, l0, h1, l1;
                split2(acc[mt][nt][0], acc[mt][nt][1], h0, l0);
                split2(acc[mt][nt][2], acc[mt][nt][3], h1, l1);
                *(uint32_t*)(Hz + (size_t)(row0 + r) * DIM + cc) = h0;
                *(uint32_t*)(Lz + (size_t)(row0 + r) * DIM + cc) = l0;
                *(uint32_t*)(Hz + (size_t)(row0 + r + 8) * DIM + cc) = h1;
                *(uint32_t*)(Lz + (size_t)(row0 + r + 8) * DIM + cc) = l1;
            }
    } else {
        __syncthreads();
        float* red = (float*)smem;           // [128][2]
        float ss[4][2];
#pragma unroll
        for (int mt = 0; mt < 4; mt++) {
            float p0 = 0.f, p1 = 0.f;
#pragma unroll
            for (int nt = 0; nt < 8; nt++) {
                p0 += acc[mt][nt][0] * acc[mt][nt][0] + acc[mt][nt][1] * acc[mt][nt][1];
                p1 += acc[mt][nt][2] * acc[mt][nt][2] + acc[mt][nt][3] * acc[mt][nt][3];
            }
            p0 += __shfl_xor_sync(0xffffffffu, p0, 1);
            p0 += __shfl_xor_sync(0xffffffffu, p0, 2);
            p1 += __shfl_xor_sync(0xffffffffu, p1, 1);
            p1 += __shfl_xor_sync(0xffffffffu, p1, 2);
            ss[mt][0] = p0; ss[mt][1] = p1;
        }
        if ((lane & 3) == 0) {
#pragma unroll
            for (int mt = 0; mt < 4; mt++) {
                int rl = m_base + mt * 16 + (lane >> 2);
                red[rl * 2 + warp_n] = ss[mt][0];
                red[(rl + 8) * 2 + warp_n] = ss[mt][1];
            }
        }
        __syncthreads();
#pragma unroll
        for (int mt = 0; mt < 4; mt++) {
            int rl = m_base + mt * 16 + (lane >> 2);
            float sm0 = red[rl * 2 + 0] + red[rl * 2 + 1];
            float sm1 = red[(rl + 8) * 2 + 0] + red[(rl + 8) * 2 + 1];
            float scl0 = rsqrtf(sm0 * (1.0f / HD) + EPSF);
            float scl1 = rsqrtf(sm1 * (1.0f / HD) + EPSF);
            int sp0 = sj + rl;
            int sp1 = sp0 + 8;
#pragma unroll
            for (int nt = 0; nt < 8; nt++) {
                int d  = n_loc + nt * 8 + ((lane & 3) << 1);
                int cc = col0 + d;
                float gd0 = Gz[d], gd1 = Gz[d + 1];
                float c0 = cosb[sp0 * (HD / 2) + (d >> 1)];
                float n0 = sinb[sp0 * (HD / 2) + (d >> 1)];
                float c1 = cosb[sp1 * (HD / 2) + (d >> 1)];
                float n1 = sinb[sp1 * (HD / 2) + (d >> 1)];
                float x0 = acc[mt][nt][0] * scl0 * gd0;
                float x1 = acc[mt][nt][1] * scl0 * gd1;
                float y0 = acc[mt][nt][2] * scl1 * gd0;
                float y1 = acc[mt][nt][3] * scl1 * gd1;
                uint32_t h0, l0, h1, l1;
                split2(x0 * c0 - x1 * n0, x0 * n0 + x1 * c0, h0, l0);
                split2(y0 * c1 - y1 * n1, y0 * n1 + y1 * c1, h1, l1);
                *(uint32_t*)(Hz + (size_t)(row0 + rl) * DIM + cc) = h0;
                *(uint32_t*)(Lz + (size_t)(row0 + rl) * DIM + cc) = l0;
                *(uint32_t*)(Hz + (size_t)(row0 + rl + 8) * DIM + cc) = h1;
                *(uint32_t*)(Lz + (size_t)(row0 + rl + 8) * DIM + cc) = l1;
            }
        }
    }
#undef ISSUE
#undef COMPUTE
}

// ===========================================================================
// Flash attention via mma.sync fp16.
// QK^T 2-pass (Qh*Kh + Ql*Kh -- K-lo dropped), PV 2-pass (Ph*Vh + Ph*Vl).
// K/V stage: Khi | Vhi | Vlo (3 x 8704 bytes). Output hi-only to Xhi.
// ===========================================================================
#define FROW_B 272
#define FK_HI 0
#define FV_HI (32 * FROW_B)
#define FV_LO (2 * 32 * FROW_B)
#define FSTAGE_B (3 * 32 * FROW_B)          // 26112
#define FNSTAGE 3
#define FLASH_SMEM_BYTES (FNSTAGE * FSTAGE_B)   // 78336 (Q staging 2*34816 fits)
#define FITERS (SEQ / 32)

__global__ void __launch_bounds__(256) flash_mma_kernel(
    const __half* __restrict__ Qhi_g, const __half* __restrict__ Qlo_g,
    const __half* __restrict__ Khi_g,
    const __half* __restrict__ Vhi_g, const __half* __restrict__ Vlo_g,
    __half* __restrict__ Ohi)
{
    extern __shared__ __align__(128) char smem[];
    const uint32_t sbase = smem_u32(smem);
    const int tid = threadIdx.x;
    const int wq = tid >> 5, lane = tid & 31;
    const int q0 = blockIdx.x * 128;
    const int bh = blockIdx.y;
    const int b = bh / HEADS, h = bh % HEADS;
    const size_t hoff = (size_t)h * HD;

    // stage Q (hi at 0, lo at +34816), pull into registers
    {
#pragma unroll
        for (int i = 0; i < 8; i++) {
            int f = tid + i * 256;
            int r = f >> 4, c = f & 15;
            uint32_t d = sbase + (uint32_t)r * FROW_B + c * 16;
            size_t so = (size_t)(b * SEQ + q0 + r) * DIM + hoff + c * 8;
            CPA16(d, (const void*)(Qhi_g + so));
            CPA16(d + 34816, (const void*)(Qlo_g + so));
        }
        CP_COMMIT();
        CP_WAIT(0);
        __syncthreads();
    }
    uint32_t qh[8][4], ql[8][4];
    {
        const uint32_t qrow = (uint32_t)(wq * 16 + (lane & 15));
        const uint32_t qc8  = (uint32_t)((lane >> 4) * 16);
#pragma unroll
        for (int ks = 0; ks < 8; ks++) {
            uint32_t ad = sbase + qrow * FROW_B + ks * 32 + qc8;
            LDM4(qh[ks], ad);
            LDM4(ql[ks], ad + 34816);
        }
    }
    __syncthreads();

#define FISSUE(kt) do { \
    const int k0 = (kt) * 32; \
    const uint32_t stb = sbase + ((kt) % FNSTAGE) * FSTAGE_B; \
    _Pragma("unroll") \
    for (int i = 0; i < 2; i++) { \
        int f = tid + i * 256; \
        int r = f >> 4, c = f & 15; \
        uint32_t d = stb + (uint32_t)r * FROW_B + c * 16; \
        size_t so = (size_t)(b * SEQ + k0 + r) * DIM + hoff + c * 8; \
        CPA16(d + FK_HI, (const void*)(Khi_g + so)); \
        CPA16(d + FV_HI, (const void*)(Vhi_g + so)); \
        CPA16(d + FV_LO, (const void*)(Vlo_g + so)); \
    } \
    CP_COMMIT(); \
} while (0)

    float acc[16][4];
#pragma unroll
    for (int i = 0; i < 16; i++)
#pragma unroll
        for (int j = 0; j < 4; j++) acc[i][j] = 0.f;
    float m0 = -1e30f, m1 = -1e30f, l0 = 0.f, l1 = 0.f;

    const uint32_t krow = (uint32_t)(lane & 15);
    const uint32_t kc8  = (uint32_t)((lane >> 4) * 16);

    FISSUE(0); FISSUE(1);
    for (int kt = 0; kt < FITERS; kt++) {
        if (kt == FITERS - 1) { CP_WAIT(0); } else { CP_WAIT(1); }
        __syncthreads();
        if (kt + 2 < FITERS) FISSUE(kt + 2);
        const uint32_t stb = sbase + (kt % FNSTAGE) * FSTAGE_B;

        // scores: 2-pass (Qh*Kh + Ql*Kh)
        float s[4][4];
#pragma unroll
        for (int i = 0; i < 4; i++)
#pragma unroll
            for (int j = 0; j < 4; j++) s[i][j] = 0.f;
#pragma unroll
        for (int ks = 0; ks < 8; ks++) {
#pragma unroll
            for (int half = 0; half < 2; half++) {
                uint32_t kbh[4];
                uint32_t kd = stb + FK_HI + (half * 16 + krow) * FROW_B + ks * 32 + kc8;
                LDM4(kbh, kd);
                MMA_F16(s[2 * half + 0], qh[ks], kbh[0], kbh[2]);
                MMA_F16(s[2 * half + 0], ql[ks], kbh[0], kbh[2]);
                MMA_F16(s[2 * half + 1], qh[ks], kbh[1], kbh[3]);
                MMA_F16(s[2 * half + 1], ql[ks], kbh[1], kbh[3]);
            }
        }
#pragma unroll
        for (int i = 0; i < 4; i++)
#pragma unroll
            for (int j = 0; j < 4; j++) s[i][j] *= SCALEF;

        // online softmax
        float mx0 = fmaxf(fmaxf(s[0][0], s[0][1]), fmaxf(s[1][0], s[1][1]));
        mx0 = fmaxf(mx0, fmaxf(fmaxf(s[2][0], s[2][1]), fmaxf(s[3][0], s[3][1])));
        float mx1 = fmaxf(fmaxf(s[0][2], s[0][3]), fmaxf(s[1][2], s[1][3]));
        mx1 = fmaxf(mx1, fmaxf(fmaxf(s[2][2], s[2][3]), fmaxf(s[3][2], s[3][3])));
#pragma unroll
        for (int o = 1; o <= 2; o <<= 1) {
            mx0 = fmaxf(mx0, __shfl_xor_sync(0xffffffffu, mx0, o));
            mx1 = fmaxf(mx1, __shfl_xor_sync(0xffffffffu, mx1, o));
        }
        float mn0 = fmaxf(m0, mx0), mn1 = fmaxf(m1, mx1);
        float f0 = __expf(m0 - mn0), f1 = __expf(m1 - mn1);
        m0 = mn0; m1 = mn1;
        float rs0 = 0.f, rs1 = 0.f;
#pragma unroll
        for (int nt = 0; nt < 4; nt++) {
            s[nt][0] = __expf(s[nt][0] - mn0);
            s[nt][1] = __expf(s[nt][1] - mn0);
            s[nt][2] = __expf(s[nt][2] - mn1);
            s[nt][3] = __expf(s[nt][3] - mn1);
            rs0 += s[nt][0] + s[nt][1];
            rs1 += s[nt][2] + s[nt][3];
        }
#pragma unroll
        for (int o = 1; o <= 2; o <<= 1) {
            rs0 += __shfl_xor_sync(0xffffffffu, rs0, o);
            rs1 += __shfl_xor_sync(0xffffffffu, rs1, o);
        }
        l0 = l0 * f0 + rs0;
        l1 = l1 * f1 + rs1;
#pragma unroll
        for (int i = 0; i < 16; i++) {
            acc[i][0] *= f0; acc[i][1] *= f0;
            acc[i][2] *= f1; acc[i][3] *= f1;
        }

        // P hi frags, PV 2-pass (Ph*Vh + Ph*Vl)
        uint32_t ph[2][4];
#pragma unroll
        for (int k2 = 0; k2 < 2; k2++) {
            ph[k2][0] = pack_h2(s[2 * k2][0],     s[2 * k2][1]);
            ph[k2][1] = pack_h2(s[2 * k2][2],     s[2 * k2][3]);
            ph[k2][2] = pack_h2(s[2 * k2 + 1][0], s[2 * k2 + 1][1]);
            ph[k2][3] = pack_h2(s[2 * k2 + 1][2], s[2 * k2 + 1][3]);
        }
#pragma unroll
        for (int ng = 0; ng < 8; ng++) {
#pragma unroll
            for (int k2 = 0; k2 < 2; k2++) {
                uint32_t vbh[4], vbl[4];
                uint32_t vd = stb + FV_HI + (k2 * 16 + krow) * FROW_B + ng * 32 + kc8;
                LDM4T(vbh, vd);
                LDM4T(vbl, vd + (FV_LO - FV_HI));
                MMA_F16(acc[2 * ng + 0], ph[k2], vbh[0], vbh[1]);
                MMA_F16(acc[2 * ng + 0], ph[k2], vbl[0], vbl[1]);
                MMA_F16(acc[2 * ng + 1], ph[k2], vbh[2], vbh[3]);
                MMA_F16(acc[2 * ng + 1], ph[k2], vbl[2], vbl[3]);
            }
        }
    }

    float inv0 = 1.0f / l0, inv1 = 1.0f / l1;
    const int r0g = b * SEQ + q0 + wq * 16 + (lane >> 2);
#pragma unroll
    for (int nt = 0; nt < 16; nt++) {
        int cc = (int)hoff + nt * 8 + ((lane & 3) << 1);
        *(uint32_t*)(Ohi + (size_t)r0g * DIM + cc) =
            pack_h2(acc[nt][0] * inv0, acc[nt][1] * inv0);
        *(uint32_t*)(Ohi + (size_t)(r0g + 8) * DIM + cc) =
            pack_h2(acc[nt][2] * inv1, acc[nt][3] * inv1);
    }
#undef FISSUE
}

// ---------------------------------------------------------------------------
extern "C" void kernel_launch(void* const* d_in, const int* in_sizes, int n_in,
                              void* d_out, int out_size)
{
    (void)in_sizes; (void)n_in; (void)out_size;
    const float* x     = (const float*)d_in[0];
    const float* ctx   = (const float*)d_in[1];
    const float* cosb  = (const float*)d_in[2];
    const float* sinb  = (const float*)d_in[3];
    const float* bq    = (const float*)d_in[5];
    const float* bk    = (const float*)d_in[7];
    const float* bv    = (const float*)d_in[9];
    const float* bqc   = (const float*)d_in[11];
    const float* bkc   = (const float*)d_in[13];
    const float* bvc   = (const float*)d_in[15];
    const float* b_out = (const float*)d_in[17];
    const float* b_add = (const float*)d_in[19];
    const float* g_q   = (const float*)d_in[20];
    const float* g_k   = (const float*)d_in[21];
    const float* g_qc  = (const float*)d_in[22];
    const float* g_kc  = (const float*)d_in[23];
    float* out = (float*)d_out;

    __half *Whi, *Xhi, *Qhi, *Qlo, *Khi, *Klo, *Vhi, *Vlo;
    cudaGetSymbolAddress((void**)&Whi, g_Whi);
    cudaGetSymbolAddress((void**)&Xhi, g_Xhi);
    cudaGetSymbolAddress((void**)&Qhi, g_Qhi);
    cudaGetSymbolAddress((void**)&Qlo, g_Qlo);
    cudaGetSymbolAddress((void**)&Khi, g_Khi);
    cudaGetSymbolAddress((void**)&Klo, g_Klo);
    cudaGetSymbolAddress((void**)&Vhi, g_Vhi);
    cudaGetSymbolAddress((void**)&Vlo, g_Vlo);

    cudaFuncSetAttribute(mma_gemm_kernel,
                         cudaFuncAttributeMaxDynamicSharedMemorySize, GEMM_SMEM_BYTES);
    cudaFuncSetAttribute(flash_mma_kernel,
                         cudaFuncAttributeMaxDynamicSharedMemorySize, FLASH_SMEM_BYTES);

    const int WN4 = DIM * DIM / 4;

    // convert all 8 weights to fp16 hi (one launch)
    conv_w8_kernel<<<dim3((WN4 + 255) / 256, 8), 256>>>(
        (const float4*)d_in[4],  (const float4*)d_in[6],  (const float4*)d_in[8],
        (const float4*)d_in[10], (const float4*)d_in[12], (const float4*)d_in[14],
        (const float4*)d_in[16], (const float4*)d_in[18],
        (uint2*)Whi, WN4);

    // activations -> fp16 hi, joint layout
    conv_hi_kernel<<<(BB * S_TXT * (DIM / 4) + 255) / 256, 256>>>(
        (const float4*)ctx, (uint2*)Xhi, S_TXT, 0);
    conv_hi_kernel<<<(BB * S_IMG * (DIM / 4) + 255) / 256, 256>>>(
        (const float4*)x, (uint2*)Xhi, S_IMG, S_TXT);

    // QKV projections: ONE launch, 128-thread CTAs (R12 config)
    dim3 gQKV(DIM / 128, (BB * SEQ) / 128, 3);
    mma_gemm_kernel<<<gQKV, 128, GEMM_SMEM_BYTES>>>(0, Xhi, Whi,
        bq, bk, bv, bqc, bkc, bvc, b_out, b_add,
        g_q, g_k, g_qc, g_kc, cosb, sinb,
        Qhi, Qlo, Khi, Klo, Vhi, Vlo, nullptr);

    // Flash attention (K-lo dropped; writes fp16 hi output into Xhi)
    flash_mma_kernel<<<dim3(SEQ / 128, BB * HEADS), 256, FLASH_SMEM_BYTES>>>(
        Qhi, Qlo, Khi, Vhi, Vlo, Xhi);

    // output projections: ONE launch
    dim3 gOut(DIM / 128, (BB * SEQ) / 128, 1);
    mma_gemm_kernel<<<gOut, 128, GEMM_SMEM_BYTES>>>(1, Xhi, Whi,
        bq, bk, bv, bqc, bkc, bvc, b_out, b_add,
        g_q, g_k, g_qc, g_kc, cosb, sinb,
        Qhi, Qlo, Khi, Klo, Vhi, Vlo, out);
}

// round 14
// speedup vs baseline: 2.3496x; 1.2191x over previous
#include <cuda_runtime.h>
#include <cuda_fp16.h>
#include <cstdint>
#include <math.h>

#define BB 2
#define S_IMG 1024
#define S_TXT 512
#define SEQ 1536
#define DIM 3072
#define HEADS 24
#define HD 128
#define EPSF 1e-6f
#define SCALEF 0.08838834764831845f

// Scratch (device globals -- no allocation allowed)
__device__ __half g_Whi[8 * DIM * DIM];
__device__ __half g_Xhi[BB * SEQ * DIM];
__device__ __half g_Qhi[BB * SEQ * DIM];
__device__ __half g_Khi[BB * SEQ * DIM];
__device__ __half g_Vhi[BB * SEQ * DIM];

// ===========================================================================
// helpers
// ===========================================================================
__device__ __forceinline__ uint32_t smem_u32(const void* p) {
    uint32_t a;
    asm("{ .reg .u64 t; cvta.to.shared.u64 t, %1; cvt.u32.u64 %0, t; }"
        : "=r"(a) : "l"(p));
    return a;
}
#define LDM4(r, a) \
    asm volatile("ldmatrix.sync.aligned.m8n8.x4.shared.b16 {%0,%1,%2,%3}, [%4];" \
        : "=r"((r)[0]), "=r"((r)[1]), "=r"((r)[2]), "=r"((r)[3]) : "r"(a))
#define LDM4T(r, a) \
    asm volatile("ldmatrix.sync.aligned.m8n8.x4.trans.shared.b16 {%0,%1,%2,%3}, [%4];" \
        : "=r"((r)[0]), "=r"((r)[1]), "=r"((r)[2]), "=r"((r)[3]) : "r"(a))
#define MMA_F16(d, a, b0, b1) \
    asm volatile("mma.sync.aligned.m16n8k16.row.col.f32.f16.f16.f32 " \
        "{%0,%1,%2,%3}, {%4,%5,%6,%7}, {%8,%9}, {%0,%1,%2,%3};" \
        : "+f"((d)[0]), "+f"((d)[1]), "+f"((d)[2]), "+f"((d)[3]) \
        : "r"((a)[0]), "r"((a)[1]), "r"((a)[2]), "r"((a)[3]), "r"(b0), "r"(b1))
#define CPA16(dst, src) \
    asm volatile("cp.async.cg.shared.global [%0], [%1], 16;" :: "r"(dst), "l"(src))
#define CP_COMMIT() asm volatile("cp.async.commit_group;" ::: "memory")
#define CP_WAIT(n)  asm volatile("cp.async.wait_group %0;" :: "n"(n) : "memory")

__device__ __forceinline__ uint32_t pack_h2(float a, float b) {
    __half2 h = __floats2half2_rn(a, b);
    return *(uint32_t*)&h;
}

// ---------------------------------------------------------------------------
// conversion kernels
// ---------------------------------------------------------------------------
__global__ void __launch_bounds__(256) conv_w8_kernel(
    const float4* __restrict__ w0, const float4* __restrict__ w1,
    const float4* __restrict__ w2, const float4* __restrict__ w3,
    const float4* __restrict__ w4, const float4* __restrict__ w5,
    const float4* __restrict__ w6, const float4* __restrict__ w7,
    uint2* __restrict__ hi, int n4)
{
    int i = blockIdx.x * 256 + threadIdx.x;
    int z = blockIdx.y;
    if (i < n4) {
        const float4* src = (z == 0) ? w0 : (z == 1) ? w1 : (z == 2) ? w2 : (z == 3) ? w3
                          : (z == 4) ? w4 : (z == 5) ? w5 : (z == 6) ? w6 : w7;
        float4 v = src[i];
        uint2 ph;
        ph.x = pack_h2(v.x, v.y);
        ph.y = pack_h2(v.z, v.w);
        hi[(size_t)z * n4 + i] = ph;
    }
}

__global__ void __launch_bounds__(256) conv_hi_kernel(
    const float4* __restrict__ src, uint2* __restrict__ hi, int rpb, int dst_off)
{
    int i = blockIdx.x * 256 + threadIdx.x;
    int n4 = BB * rpb * (DIM / 4);
    if (i < n4) {
        int q = i % (DIM / 4);
        int row = i / (DIM / 4);
        int b = row / rpb, s = row % rpb;
        float4 v = src[i];
        uint2 ph;
        ph.x = pack_h2(v.x, v.y);
        ph.y = pack_h2(v.z, v.w);
        hi[(b * SEQ + dst_off + s) * (DIM / 4) + q] = ph;
    }
}

// ===========================================================================
// fp16 1-pass GEMM, tile 128x128, 128 threads = 4 warps each owning 64x64
// (R12/R13-proven). KC=32, 5-stage cp.async. Fused epilogues (hi-only out).
// ===========================================================================
#define KC 32
#define CHUNKS (DIM / KC)                  // 96
#define A_ST2 80
#define B_ST2 272
#define A_TILE_B (128 * A_ST2)              // 10240
#define B_TILE_B (32 * B_ST2)               // 8704
#define OFF_BHI A_TILE_B
#define STAGE_B (A_TILE_B + B_TILE_B)       // 18944
#define NSTAGE 5
#define GEMM_SMEM_BYTES (NSTAGE * STAGE_B)  // 94720

__global__ void __launch_bounds__(128, 2) mma_gemm_kernel(
    int mode,
    const __half* __restrict__ Xg,
    const __half* __restrict__ Whi_base,
    const float* bq, const float* bk, const float* bv,
    const float* bqc, const float* bkc, const float* bvc,
    const float* b_out, const float* b_add,
    const float* g_q, const float* g_k, const float* g_qc, const float* g_kc,
    const float* __restrict__ cosb, const float* __restrict__ sinb,
    __half* Qhi, __half* Khi, __half* Vhi,
    float* out)
{
    extern __shared__ __align__(128) char smem[];
    const uint32_t sbase = smem_u32(smem);
    const int tid = threadIdx.x;
    const int wid = tid >> 5, lane = tid & 31;
    const int warp_m = wid >> 1;
    const int warp_n = wid & 1;
    const int z = blockIdx.z;

    const int row0 = blockIdx.y * 128;
    const int col0 = blockIdx.x * 128;
    const int b  = row0 / SEQ;
    const int sj = row0 % SEQ;
    const bool txt = (sj < S_TXT);

    int widx;
    const float* bias;
    __half* Hz = nullptr;
    const float* Gz = nullptr;
    float* C = nullptr;
    if (mode == 0) {
        widx = txt ? (3 + z) : z;
        bias = (z == 0) ? (txt ? bqc : bq) : (z == 1) ? (txt ? bkc : bk) : (txt ? bvc : bv);
        Hz = (z == 0) ? Qhi : (z == 1) ? Khi : Vhi;
        Gz = (z == 0) ? (txt ? g_qc : g_q) : (z == 1) ? (txt ? g_kc : g_k) : nullptr;
    } else {
        widx = txt ? 7 : 6;
        bias = txt ? b_add : b_out;
        size_t crow = txt ? (size_t)(b * S_TXT + sj)
                          : (size_t)(BB * S_TXT + b * S_IMG + (sj - S_TXT));
        C = out + crow * DIM;
    }
    const __half* Whi = Whi_base + (size_t)widx * DIM * DIM;
    const __half* Ahi = Xg + (size_t)row0 * DIM;

#define ISSUE(c) do { \
    const int k0 = (c) * KC; \
    const uint32_t stb = sbase + ((c) % NSTAGE) * STAGE_B; \
    _Pragma("unroll") \
    for (int i = 0; i < 4; i++) { \
        int f = tid + i * 128; \
        uint32_t d = stb + (uint32_t)(f >> 2) * A_ST2 + (f & 3) * 16; \
        size_t so = (size_t)(f >> 2) * DIM + k0 + ((f & 3) << 3); \
        CPA16(d, (const void*)(Ahi + so)); \
        uint32_t db = stb + OFF_BHI + (uint32_t)(f >> 4) * B_ST2 + (f & 15) * 16; \
        size_t sb2 = (size_t)(k0 + (f >> 4)) * DIM + col0 + ((f & 15) << 3); \
        CPA16(db, (const void*)(Whi + sb2)); \
    } \
    CP_COMMIT(); \
} while (0)

    float acc[4][8][4];
#pragma unroll
    for (int i = 0; i < 4; i++)
#pragma unroll
        for (int j = 0; j < 8; j++)
#pragma unroll
            for (int k = 0; k < 4; k++) acc[i][j][k] = 0.f;

    const uint32_t a_row = (uint32_t)(warp_m * 64 + (lane & 15));
    const uint32_t a_sel = (uint32_t)((lane >> 4) * 16);
    const uint32_t b_row = (uint32_t)(lane & 15);
    const uint32_t b_sel = (uint32_t)(warp_n * 128 + ((lane >> 4) * 16));

#define COMPUTE(sidx) do { \
    const uint32_t sb = sbase + (sidx) * STAGE_B; \
    _Pragma("unroll") \
    for (int ks = 0; ks < 2; ks++) { \
        uint32_t ah[4][4]; \
        _Pragma("unroll") \
        for (int mt = 0; mt < 4; mt++) { \
            uint32_t ad = sb + (a_row + mt * 16) * A_ST2 + ks * 32 + a_sel; \
            LDM4(ah[mt], ad); \
        } \
        _Pragma("unroll") \
        for (int ng = 0; ng < 4; ng++) { \
            uint32_t bh[4]; \
            uint32_t bd = sb + OFF_BHI + (ks * 16 + b_row) * B_ST2 + b_sel + ng * 32; \
            LDM4T(bh, bd); \
            _Pragma("unroll") \
            for (int mt = 0; mt < 4; mt++) { \
                MMA_F16(acc[mt][ng * 2 + 0], ah[mt], bh[0], bh[1]); \
                MMA_F16(acc[mt][ng * 2 + 1], ah[mt], bh[2], bh[3]); \
            } \
        } \
    } \
} while (0)

    ISSUE(0); ISSUE(1); ISSUE(2); ISSUE(3);
    for (int c = 0; c < CHUNKS; c++) {
        if (c < CHUNKS - 3)      { CP_WAIT(3); }
        else if (c == CHUNKS - 3){ CP_WAIT(2); }
        else if (c == CHUNKS - 2){ CP_WAIT(1); }
        else                     { CP_WAIT(0); }
        __syncthreads();
        if (c + 4 < CHUNKS) ISSUE(c + 4);
        COMPUTE(c % NSTAGE);
    }

    // ---------------- epilogue ----------------
    const int m_base = warp_m * 64;
    const int n_loc  = warp_n * 64;

#pragma unroll
    for (int mt = 0; mt < 4; mt++)
#pragma unroll
        for (int nt = 0; nt < 8; nt++) {
            int cc = col0 + n_loc + nt * 8 + ((lane & 3) << 1);
            float b0 = bias[cc], b1 = bias[cc + 1];
            acc[mt][nt][0] += b0; acc[mt][nt][1] += b1;
            acc[mt][nt][2] += b0; acc[mt][nt][3] += b1;
        }

    if (mode == 1) {
#pragma unroll
        for (int mt = 0; mt < 4; mt++)
#pragma unroll
            for (int nt = 0; nt < 8; nt++) {
                int r  = m_base + mt * 16 + (lane >> 2);
                int cc = col0 + n_loc + nt * 8 + ((lane & 3) << 1);
                *(float2*)(C + (size_t)r * DIM + cc) =
                    make_float2(acc[mt][nt][0], acc[mt][nt][1]);
                *(float2*)(C + (size_t)(r + 8) * DIM + cc) =
                    make_float2(acc[mt][nt][2], acc[mt][nt][3]);
            }
    } else if (Gz == nullptr) {
        // V path: fp16 hi
#pragma unroll
        for (int mt = 0; mt < 4; mt++)
#pragma unroll
            for (int nt = 0; nt < 8; nt++) {
                int r  = m_base + mt * 16 + (lane >> 2);
                int cc = col0 + n_loc + nt * 8 + ((lane & 3) << 1);
                *(uint32_t*)(Hz + (size_t)(row0 + r) * DIM + cc) =
                    pack_h2(acc[mt][nt][0], acc[mt][nt][1]);
                *(uint32_t*)(Hz + (size_t)(row0 + r + 8) * DIM + cc) =
                    pack_h2(acc[mt][nt][2], acc[mt][nt][3]);
            }
    } else {
        // Q/K path: RMS-norm over the 128-col head + RoPE, fp16 hi out
        __syncthreads();
        float* red = (float*)smem;           // [128][2]
        float ss[4][2];
#pragma unroll
        for (int mt = 0; mt < 4; mt++) {
            float p0 = 0.f, p1 = 0.f;
#pragma unroll
            for (int nt = 0; nt < 8; nt++) {
                p0 += acc[mt][nt][0] * acc[mt][nt][0] + acc[mt][nt][1] * acc[mt][nt][1];
                p1 += acc[mt][nt][2] * acc[mt][nt][2] + acc[mt][nt][3] * acc[mt][nt][3];
            }
            p0 += __shfl_xor_sync(0xffffffffu, p0, 1);
            p0 += __shfl_xor_sync(0xffffffffu, p0, 2);
            p1 += __shfl_xor_sync(0xffffffffu, p1, 1);
            p1 += __shfl_xor_sync(0xffffffffu, p1, 2);
            ss[mt][0] = p0; ss[mt][1] = p1;
        }
        if ((lane & 3) == 0) {
#pragma unroll
            for (int mt = 0; mt < 4; mt++) {
                int rl = m_base + mt * 16 + (lane >> 2);
                red[rl * 2 + warp_n] = ss[mt][0];
                red[(rl + 8) * 2 + warp_n] = ss[mt][1];
            }
        }
        __syncthreads();
#pragma unroll
        for (int mt = 0; mt < 4; mt++) {
            int rl = m_base + mt * 16 + (lane >> 2);
            float sm0 = red[rl * 2 + 0] + red[rl * 2 + 1];
            float sm1 = red[(rl + 8) * 2 + 0] + red[(rl + 8) * 2 + 1];
            float scl0 = rsqrtf(sm0 * (1.0f / HD) + EPSF);
            float scl1 = rsqrtf(sm1 * (1.0f / HD) + EPSF);
            int sp0 = sj + rl;
            int sp1 = sp0 + 8;
#pragma unroll
            for (int nt = 0; nt < 8; nt++) {
                int d  = n_loc + nt * 8 + ((lane & 3) << 1);
                int cc = col0 + d;
                float gd0 = Gz[d], gd1 = Gz[d + 1];
                float c0 = cosb[sp0 * (HD / 2) + (d >> 1)];
                float n0 = sinb[sp0 * (HD / 2) + (d >> 1)];
                float c1 = cosb[sp1 * (HD / 2) + (d >> 1)];
                float n1 = sinb[sp1 * (HD / 2) + (d >> 1)];
                float x0 = acc[mt][nt][0] * scl0 * gd0;
                float x1 = acc[mt][nt][1] * scl0 * gd1;
                float y0 = acc[mt][nt][2] * scl1 * gd0;
                float y1 = acc[mt][nt][3] * scl1 * gd1;
                *(uint32_t*)(Hz + (size_t)(row0 + rl) * DIM + cc) =
                    pack_h2(x0 * c0 - x1 * n0, x0 * n0 + x1 * c0);
                *(uint32_t*)(Hz + (size_t)(row0 + rl + 8) * DIM + cc) =
                    pack_h2(y0 * c1 - y1 * n1, y0 * n1 + y1 * c1);
            }
        }
    }
#undef ISSUE
#undef COMPUTE
}

// ===========================================================================
// Flash attention via mma.sync, pure fp16 (Q/K/V/P all hi).
// BM=128 (8 warps x 16 rows), BN=32, HD=128. 4-stage K/V pipeline.
// K/V stage: Khi | Vhi (2 x 8704 bytes). Output hi-only to Xhi.
// ===========================================================================
#define FROW_B 272
#define FK_HI 0
#define FV_HI (32 * FROW_B)
#define FSTAGE_B (2 * 32 * FROW_B)          // 17408
#define FNSTAGE 4
#define FLASH_SMEM_BYTES (FNSTAGE * FSTAGE_B)   // 69632 (>= Q staging 34816)
#define FITERS (SEQ / 32)

__global__ void __launch_bounds__(256) flash_mma_kernel(
    const __half* __restrict__ Qhi_g,
    const __half* __restrict__ Khi_g,
    const __half* __restrict__ Vhi_g,
    __half* __restrict__ Ohi)
{
    extern __shared__ __align__(128) char smem[];
    const uint32_t sbase = smem_u32(smem);
    const int tid = threadIdx.x;
    const int wq = tid >> 5, lane = tid & 31;
    const int q0 = blockIdx.x * 128;
    const int bh = blockIdx.y;
    const int b = bh / HEADS, h = bh % HEADS;
    const size_t hoff = (size_t)h * HD;

    // stage Q (hi only), pull into registers
    {
#pragma unroll
        for (int i = 0; i < 8; i++) {
            int f = tid + i * 256;
            int r = f >> 4, c = f & 15;
            uint32_t d = sbase + (uint32_t)r * FROW_B + c * 16;
            size_t so = (size_t)(b * SEQ + q0 + r) * DIM + hoff + c * 8;
            CPA16(d, (const void*)(Qhi_g + so));
        }
        CP_COMMIT();
        CP_WAIT(0);
        __syncthreads();
    }
    uint32_t qh[8][4];
    {
        const uint32_t qrow = (uint32_t)(wq * 16 + (lane & 15));
        const uint32_t qc8  = (uint32_t)((lane >> 4) * 16);
#pragma unroll
        for (int ks = 0; ks < 8; ks++) {
            uint32_t ad = sbase + qrow * FROW_B + ks * 32 + qc8;
            LDM4(qh[ks], ad);
        }
    }
    __syncthreads();

#define FISSUE(kt) do { \
    const int k0 = (kt) * 32; \
    const uint32_t stb = sbase + ((kt) % FNSTAGE) * FSTAGE_B; \
    _Pragma("unroll") \
    for (int i = 0; i < 2; i++) { \
        int f = tid + i * 256; \
        int r = f >> 4, c = f & 15; \
        uint32_t d = stb + (uint32_t)r * FROW_B + c * 16; \
        size_t so = (size_t)(b * SEQ + k0 + r) * DIM + hoff + c * 8; \
        CPA16(d + FK_HI, (const void*)(Khi_g + so)); \
        CPA16(d + FV_HI, (const void*)(Vhi_g + so)); \
    } \
    CP_COMMIT(); \
} while (0)

    float acc[16][4];
#pragma unroll
    for (int i = 0; i < 16; i++)
#pragma unroll
        for (int j = 0; j < 4; j++) acc[i][j] = 0.f;
    float m0 = -1e30f, m1 = -1e30f, l0 = 0.f, l1 = 0.f;

    const uint32_t krow = (uint32_t)(lane & 15);
    const uint32_t kc8  = (uint32_t)((lane >> 4) * 16);

    FISSUE(0); FISSUE(1); FISSUE(2);
    for (int kt = 0; kt < FITERS; kt++) {
        if (kt < FITERS - 2)      { CP_WAIT(2); }
        else if (kt == FITERS - 2){ CP_WAIT(1); }
        else                      { CP_WAIT(0); }
        __syncthreads();
        if (kt + 3 < FITERS) FISSUE(kt + 3);
        const uint32_t stb = sbase + (kt % FNSTAGE) * FSTAGE_B;

        // scores: 1-pass fp16
        float s[4][4];
#pragma unroll
        for (int i = 0; i < 4; i++)
#pragma unroll
            for (int j = 0; j < 4; j++) s[i][j] = 0.f;
#pragma unroll
        for (int ks = 0; ks < 8; ks++) {
#pragma unroll
            for (int half = 0; half < 2; half++) {
                uint32_t kbh[4];
                uint32_t kd = stb + FK_HI + (half * 16 + krow) * FROW_B + ks * 32 + kc8;
                LDM4(kbh, kd);
                MMA_F16(s[2 * half + 0], qh[ks], kbh[0], kbh[2]);
                MMA_F16(s[2 * half + 1], qh[ks], kbh[1], kbh[3]);
            }
        }
#pragma unroll
        for (int i = 0; i < 4; i++)
#pragma unroll
            for (int j = 0; j < 4; j++) s[i][j] *= SCALEF;

        // online softmax
        float mx0 = fmaxf(fmaxf(s[0][0], s[0][1]), fmaxf(s[1][0], s[1][1]));
        mx0 = fmaxf(mx0, fmaxf(fmaxf(s[2][0], s[2][1]), fmaxf(s[3][0], s[3][1])));
        float mx1 = fmaxf(fmaxf(s[0][2], s[0][3]), fmaxf(s[1][2], s[1][3]));
        mx1 = fmaxf(mx1, fmaxf(fmaxf(s[2][2], s[2][3]), fmaxf(s[3][2], s[3][3])));
#pragma unroll
        for (int o = 1; o <= 2; o <<= 1) {
            mx0 = fmaxf(mx0, __shfl_xor_sync(0xffffffffu, mx0, o));
            mx1 = fmaxf(mx1, __shfl_xor_sync(0xffffffffu, mx1, o));
        }
        float mn0 = fmaxf(m0, mx0), mn1 = fmaxf(m1, mx1);
        float f0 = __expf(m0 - mn0), f1 = __expf(m1 - mn1);
        m0 = mn0; m1 = mn1;
        float rs0 = 0.f, rs1 = 0.f;
#pragma unroll
        for (int nt = 0; nt < 4; nt++) {
            s[nt][0] = __expf(s[nt][0] - mn0);
            s[nt][1] = __expf(s[nt][1] - mn0);
            s[nt][2] = __expf(s[nt][2] - mn1);
            s[nt][3] = __expf(s[nt][3] - mn1);
            rs0 += s[nt][0] + s[nt][1];
            rs1 += s[nt][2] + s[nt][3];
        }
#pragma unroll
        for (int o = 1; o <= 2; o <<= 1) {
            rs0 += __shfl_xor_sync(0xffffffffu, rs0, o);
            rs1 += __shfl_xor_sync(0xffffffffu, rs1, o);
        }
        l0 = l0 * f0 + rs0;
        l1 = l1 * f1 + rs1;
#pragma unroll
        for (int i = 0; i < 16; i++) {
            acc[i][0] *= f0; acc[i][1] *= f0;
            acc[i][2] *= f1; acc[i][3] *= f1;
        }

        // P hi frags, PV 1-pass
        uint32_t ph[2][4];
#pragma unroll
        for (int k2 = 0; k2 < 2; k2++) {
            ph[k2][0] = pack_h2(s[2 * k2][0],     s[2 * k2][1]);
            ph[k2][1] = pack_h2(s[2 * k2][2],     s[2 * k2][3]);
            ph[k2][2] = pack_h2(s[2 * k2 + 1][0], s[2 * k2 + 1][1]);
            ph[k2][3] = pack_h2(s[2 * k2 + 1][2], s[2 * k2 + 1][3]);
        }
#pragma unroll
        for (int ng = 0; ng < 8; ng++) {
#pragma unroll
            for (int k2 = 0; k2 < 2; k2++) {
                uint32_t vbh[4];
                uint32_t vd = stb + FV_HI + (k2 * 16 + krow) * FROW_B + ng * 32 + kc8;
                LDM4T(vbh, vd);
                MMA_F16(acc[2 * ng + 0], ph[k2], vbh[0], vbh[1]);
                MMA_F16(acc[2 * ng + 1], ph[k2], vbh[2], vbh[3]);
            }
        }
    }

    float inv0 = 1.0f / l0, inv1 = 1.0f / l1;
    const int r0g = b * SEQ + q0 + wq * 16 + (lane >> 2);
#pragma unroll
    for (int nt = 0; nt < 16; nt++) {
        int cc = (int)hoff + nt * 8 + ((lane & 3) << 1);
        *(uint32_t*)(Ohi + (size_t)r0g * DIM + cc) =
            pack_h2(acc[nt][0] * inv0, acc[nt][1] * inv0);
        *(uint32_t*)(Ohi + (size_t)(r0g + 8) * DIM + cc) =
            pack_h2(acc[nt][2] * inv1, acc[nt][3] * inv1);
    }
#undef FISSUE
}

// ---------------------------------------------------------------------------
extern "C" void kernel_launch(void* const* d_in, const int* in_sizes, int n_in,
                              void* d_out, int out_size)
{
    (void)in_sizes; (void)n_in; (void)out_size;
    const float* x     = (const float*)d_in[0];
    const float* ctx   = (const float*)d_in[1];
    const float* cosb  = (const float*)d_in[2];
    const float* sinb  = (const float*)d_in[3];
    const float* bq    = (const float*)d_in[5];
    const float* bk    = (const float*)d_in[7];
    const float* bv    = (const float*)d_in[9];
    const float* bqc   = (const float*)d_in[11];
    const float* bkc   = (const float*)d_in[13];
    const float* bvc   = (const float*)d_in[15];
    const float* b_out = (const float*)d_in[17];
    const float* b_add = (const float*)d_in[19];
    const float* g_q   = (const float*)d_in[20];
    const float* g_k   = (const float*)d_in[21];
    const float* g_qc  = (const float*)d_in[22];
    const float* g_kc  = (const float*)d_in[23];
    float* out = (float*)d_out;

    __half *Whi, *Xhi, *Qhi, *Khi, *Vhi;
    cudaGetSymbolAddress((void**)&Whi, g_Whi);
    cudaGetSymbolAddress((void**)&Xhi, g_Xhi);
    cudaGetSymbolAddress((void**)&Qhi, g_Qhi);
    cudaGetSymbolAddress((void**)&Khi, g_Khi);
    cudaGetSymbolAddress((void**)&Vhi, g_Vhi);

    cudaFuncSetAttribute(mma_gemm_kernel,
                         cudaFuncAttributeMaxDynamicSharedMemorySize, GEMM_SMEM_BYTES);
    cudaFuncSetAttribute(flash_mma_kernel,
                         cudaFuncAttributeMaxDynamicSharedMemorySize, FLASH_SMEM_BYTES);

    const int WN4 = DIM * DIM / 4;

    // convert all 8 weights to fp16 hi (one launch)
    conv_w8_kernel<<<dim3((WN4 + 255) / 256, 8), 256>>>(
        (const float4*)d_in[4],  (const float4*)d_in[6],  (const float4*)d_in[8],
        (const float4*)d_in[10], (const float4*)d_in[12], (const float4*)d_in[14],
        (const float4*)d_in[16], (const float4*)d_in[18],
        (uint2*)Whi, WN4);

    // activations -> fp16 hi, joint layout
    conv_hi_kernel<<<(BB * S_TXT * (DIM / 4) + 255) / 256, 256>>>(
        (const float4*)ctx, (uint2*)Xhi, S_TXT, 0);
    conv_hi_kernel<<<(BB * S_IMG * (DIM / 4) + 255) / 256, 256>>>(
        (const float4*)x, (uint2*)Xhi, S_IMG, S_TXT);

    // QKV projections: ONE launch, 128-thread CTAs
    dim3 gQKV(DIM / 128, (BB * SEQ) / 128, 3);
    mma_gemm_kernel<<<gQKV, 128, GEMM_SMEM_BYTES>>>(0, Xhi, Whi,
        bq, bk, bv, bqc, bkc, bvc, b_out, b_add,
        g_q, g_k, g_qc, g_kc, cosb, sinb,
        Qhi, Khi, Vhi, nullptr);

    // Flash attention (pure fp16; writes hi output into Xhi)
    flash_mma_kernel<<<dim3(SEQ / 128, BB * HEADS), 256, FLASH_SMEM_BYTES>>>(
        Qhi, Khi, Vhi, Xhi);

    // output projections: ONE launch
    dim3 gOut(DIM / 128, (BB * SEQ) / 128, 1);
    mma_gemm_kernel<<<gOut, 128, GEMM_SMEM_BYTES>>>(1, Xhi, Whi,
        bq, bk, bv, bqc, bkc, bvc, b_out, b_add,
        g_q, g_k, g_qc, g_kc, cosb, sinb,
        Qhi, Khi, Vhi, out);
}